// round 9
// baseline (speedup 1.0000x reference)
#include <cuda_runtime.h>
#include <cuda_bf16.h>
#include <math.h>

#define BB 4
#define CC 64
#define NN 4096
typedef unsigned int u32;

__device__ __nv_bfloat16 g_QTh[(size_t)BB*NN*CC];
__device__ __nv_bfloat16 g_QTl[(size_t)BB*NN*CC];
__device__ __nv_bfloat16 g_KTh[(size_t)BB*NN*CC];
__device__ __nv_bfloat16 g_KTl[(size_t)BB*NN*CC];
__device__ __nv_bfloat16 g_Vh [(size_t)BB*CC*NN];
__device__ __nv_bfloat16 g_Vl [(size_t)BB*CC*NN];

__device__ __forceinline__ u32 smem_u32(const void* p){
    u32 a; asm("{ .reg .u64 t; cvta.to.shared.u64 t, %1; cvt.u32.u64 %0, t; }":"=r"(a):"l"(p)); return a;
}
__device__ __forceinline__ u32 pkbf2(float e0, float e1){     // lo=e0, hi=e1
    u32 r; asm("cvt.rn.bf16x2.f32 %0, %1, %2;" : "=r"(r) : "f"(e1), "f"(e0)); return r;
}
__device__ __forceinline__ float bfround(float a){
    return __bfloat162float(__float2bfloat16_rn(a));
}
#define LDSM4(r0,r1,r2,r3,addr) \
    asm volatile("ldmatrix.sync.aligned.m8n8.x4.shared.b16 {%0,%1,%2,%3},[%4];" \
        : "=r"(r0),"=r"(r1),"=r"(r2),"=r"(r3) : "r"(addr))
#define MMA(d,a0,a1,a2,a3,b0,b1) \
    asm volatile("mma.sync.aligned.m16n8k16.row.col.f32.bf16.bf16.f32 " \
        "{%0,%1,%2,%3},{%4,%5,%6,%7},{%8,%9},{%0,%1,%2,%3};" \
        : "+f"((d)[0]),"+f"((d)[1]),"+f"((d)[2]),"+f"((d)[3]) \
        : "r"(a0),"r"(a1),"r"(a2),"r"(a3),"r"(b0),"r"(b1))

__device__ __forceinline__ void split2(float a0, float a1, u32& hi, u32& lo){
    float h0 = bfround(a0), h1 = bfround(a1);
    hi = pkbf2(h0, h1);
    lo = pkbf2(a0 - h0, a1 - h1);
}

// smem byte offsets (attn): K rows stride 144B (72 bf16), V rows stride 272B
#define SK_H 0
#define SK_L 18432
#define SV_H 36864
#define SV_L 54272
#define SMEM2 71680

// ------------------- Kernel 1: QKV + bf16 hi/lo split -------------------
__global__ void __launch_bounds__(256) qkv_kernel(
    const float* __restrict__ x,
    const float* __restrict__ Wq, const float* __restrict__ bq,
    const float* __restrict__ Wk, const float* __restrict__ bk,
    const float* __restrict__ Wv, const float* __restrict__ bv)
{
    extern __shared__ float sm1[];
    float* xs  = sm1;            // [64][128] then staging [128][64]
    float* wtq = sm1 + 8192;
    float* wtk = wtq + 64*68;
    float* wtv = wtk + 64*68;
    const int t = threadIdx.x, b = blockIdx.y, nbase = blockIdx.x*128;

    for (int idx = t; idx < 64*64; idx += 256) {
        int o = idx>>6, c = idx&63;
        wtq[c*68+o]=Wq[idx]; wtk[c*68+o]=Wk[idx]; wtv[c*68+o]=Wv[idx];
    }
    const float* xb = x + (size_t)b*CC*NN + nbase;
    for (int i4 = t; i4 < 2048; i4 += 256) {
        int c = i4>>5, n4 = (i4&31)<<2;
        *(float4*)&xs[c*128+n4] = *(const float4*)&xb[(size_t)c*NN+n4];
    }
    __syncthreads();
    const int ty = t>>4, tx = t&15, o0 = ty*4, n0 = tx*8;
    float aq[4][8], ak[4][8], av[4][8];
    #pragma unroll
    for (int r = 0; r < 4; r++) {
        float vq=bq[o0+r], vk=bk[o0+r], vv=bv[o0+r];
        #pragma unroll
        for (int s = 0; s < 8; s++){ aq[r][s]=vq; ak[r][s]=vk; av[r][s]=vv; }
    }
    #pragma unroll 4
    for (int c = 0; c < 64; c++) {
        float wqa[4],wka[4],wva[4],xr[8];
        *(float4*)&wqa[0]=*(float4*)&wtq[c*68+o0];
        *(float4*)&wka[0]=*(float4*)&wtk[c*68+o0];
        *(float4*)&wva[0]=*(float4*)&wtv[c*68+o0];
        *(float4*)&xr[0]=*(float4*)&xs[c*128+n0];
        *(float4*)&xr[4]=*(float4*)&xs[c*128+n0+4];
        #pragma unroll
        for (int r = 0; r < 4; r++)
            #pragma unroll
            for (int s = 0; s < 8; s++){
                aq[r][s]+=wqa[r]*xr[s]; ak[r][s]+=wka[r]*xr[s]; av[r][s]+=wva[r]*xr[s];
            }
    }
    // V: natural [c][n]
    #pragma unroll
    for (int r = 0; r < 4; r++) {
        size_t off = (size_t)b*CC*NN + (size_t)(o0+r)*NN + nbase + n0;
        #pragma unroll
        for (int m = 0; m < 4; m++) {
            u32 hi, lo; split2(av[r][2*m], av[r][2*m+1], hi, lo);
            *(u32*)(g_Vh+off+2*m) = hi; *(u32*)(g_Vl+off+2*m) = lo;
        }
    }
    // Q transposed [n][c]
    __syncthreads();
    #pragma unroll
    for (int r = 0; r < 4; r++)
        #pragma unroll
        for (int s = 0; s < 8; s++) xs[(n0+s)*64+o0+r] = aq[r][s];
    __syncthreads();
    {
        int n = t>>1, cb = (t&1)*32;
        const float* src = &xs[n*64+cb];
        size_t gb = ((size_t)b*NN + nbase + n)*CC + cb;
        #pragma unroll
        for (int m = 0; m < 16; m++) {
            u32 hi, lo; split2(src[2*m], src[2*m+1], hi, lo);
            *(u32*)(g_QTh+gb+2*m) = hi; *(u32*)(g_QTl+gb+2*m) = lo;
        }
    }
    __syncthreads();
    #pragma unroll
    for (int r = 0; r < 4; r++)
        #pragma unroll
        for (int s = 0; s < 8; s++) xs[(n0+s)*64+o0+r] = ak[r][s];
    __syncthreads();
    {
        int n = t>>1, cb = (t&1)*32;
        const float* src = &xs[n*64+cb];
        size_t gb = ((size_t)b*NN + nbase + n)*CC + cb;
        #pragma unroll
        for (int m = 0; m < 16; m++) {
            u32 hi, lo; split2(src[2*m], src[2*m+1], hi, lo);
            *(u32*)(g_KTh+gb+2*m) = hi; *(u32*)(g_KTl+gb+2*m) = lo;
        }
    }
}

// ------------------- Kernel 2: HMMA flash attention, 2 CTAs/SM -------------------
// 64 q-rows/CTA, 4 warps (warp owns 16 rows), 128 threads, grid (64,4).
// Two CTAs co-resident per SM -> independent barrier domains overlap
// load/exp phases of one CTA with MMA streams of the other.
__global__ void __launch_bounds__(128, 2) attn_kernel(
    const float* __restrict__ x, const float* __restrict__ gamma,
    float* __restrict__ out)
{
    extern __shared__ __align__(16) char sm2[];
    const u32 sb = smem_u32(sm2);
    const int t = threadIdx.x, wid = t>>5, lane = t&31;
    const int i0 = wid*16;
    const int b = blockIdx.y, ibase = blockIdx.x*64;

    const __nv_bfloat16* qh = g_QTh + (size_t)b*NN*CC;
    const __nv_bfloat16* ql = g_QTl + (size_t)b*NN*CC;
    const __nv_bfloat16* kh = g_KTh + (size_t)b*NN*CC;
    const __nv_bfloat16* kl = g_KTl + (size_t)b*NN*CC;
    const __nv_bfloat16* vh = g_Vh  + (size_t)b*CC*NN;
    const __nv_bfloat16* vl = g_Vl  + (size_t)b*CC*NN;

    // ---- stage Q [64][64] hi/lo into K area, pull A-frags into regs ----
    #pragma unroll
    for (int k = 0; k < 4; k++) {
        int idx = t + k*128, row = idx>>3, ch = idx&7;
        *(float4*)(sm2 + SK_H + row*144 + ch*16) = ((const float4*)(qh + (size_t)(ibase+row)*CC))[ch];
        *(float4*)(sm2 + SK_L + row*144 + ch*16) = ((const float4*)(ql + (size_t)(ibase+row)*CC))[ch];
    }
    __syncthreads();
    u32 qfh[4][4], qfl[4][4];
    {
        u32 abase = sb + (u32)((i0 + (lane&15))*144 + ((lane>>4)*16));
        #pragma unroll
        for (int ks = 0; ks < 4; ks++) {
            LDSM4(qfh[ks][0],qfh[ks][1],qfh[ks][2],qfh[ks][3], abase + ks*32);
            LDSM4(qfl[ks][0],qfl[ks][1],qfl[ks][2],qfl[ks][3], abase + ks*32 + 18432);
        }
    }
    __syncthreads();

    float O[8][4];
    #pragma unroll
    for (int nb = 0; nb < 8; nb++)
        #pragma unroll
        for (int k = 0; k < 4; k++) O[nb][k] = 0.f;
    float s0 = 0.f, s1 = 0.f;

    for (int tile = 0; tile < 32; tile++) {
        const int jt = tile << 7;
        // ---- g2s: K tile [128 j][64 c], V tile [64 c][128 j], hi+lo ----
        #pragma unroll
        for (int k = 0; k < 8; k++) {
            int idx = t + k*128, row = idx>>3, ch = idx&7;
            *(float4*)(sm2 + SK_H + row*144 + ch*16) = ((const float4*)(kh + (size_t)(jt+row)*CC))[ch];
            *(float4*)(sm2 + SK_L + row*144 + ch*16) = ((const float4*)(kl + (size_t)(jt+row)*CC))[ch];
        }
        #pragma unroll
        for (int k = 0; k < 8; k++) {
            int idx = t + k*128, row = idx>>4, ch = idx&15;
            *(float4*)(sm2 + SV_H + row*272 + ch*16) = ((const float4*)(vh + (size_t)row*NN + jt))[ch];
            *(float4*)(sm2 + SV_L + row*272 + ch*16) = ((const float4*)(vl + (size_t)row*NN + jt))[ch];
        }
        __syncthreads();

        // ---- GEMM1: S[16 x 128] = Qh*Kh + Qh*Kl + Ql*Kh ----
        float S[16][4];
        #pragma unroll
        for (int nb = 0; nb < 16; nb++) {
            #pragma unroll
            for (int k = 0; k < 4; k++) S[nb][k] = 0.f;
            u32 base = sb + SK_H + (u32)((nb*8 + (lane&7))*144 + ((lane>>3)*16));
            u32 h0,h1,h2,h3,h4,h5,h6,h7, l0,l1,l2,l3,l4,l5,l6,l7;
            LDSM4(h0,h1,h2,h3, base);
            LDSM4(h4,h5,h6,h7, base + 64);
            LDSM4(l0,l1,l2,l3, base + 18432);
            LDSM4(l4,l5,l6,l7, base + 18432 + 64);
            MMA(S[nb], qfh[0][0],qfh[0][1],qfh[0][2],qfh[0][3], h0,h1);
            MMA(S[nb], qfh[1][0],qfh[1][1],qfh[1][2],qfh[1][3], h2,h3);
            MMA(S[nb], qfh[2][0],qfh[2][1],qfh[2][2],qfh[2][3], h4,h5);
            MMA(S[nb], qfh[3][0],qfh[3][1],qfh[3][2],qfh[3][3], h6,h7);
            MMA(S[nb], qfh[0][0],qfh[0][1],qfh[0][2],qfh[0][3], l0,l1);
            MMA(S[nb], qfh[1][0],qfh[1][1],qfh[1][2],qfh[1][3], l2,l3);
            MMA(S[nb], qfh[2][0],qfh[2][1],qfh[2][2],qfh[2][3], l4,l5);
            MMA(S[nb], qfh[3][0],qfh[3][1],qfh[3][2],qfh[3][3], l6,l7);
            MMA(S[nb], qfl[0][0],qfl[0][1],qfl[0][2],qfl[0][3], h0,h1);
            MMA(S[nb], qfl[1][0],qfl[1][1],qfl[1][2],qfl[1][3], h2,h3);
            MMA(S[nb], qfl[2][0],qfl[2][1],qfl[2][2],qfl[2][3], h4,h5);
            MMA(S[nb], qfl[3][0],qfl[3][1],qfl[3][2],qfl[3][3], h6,h7);
        }

        // ---- exp (unnormalized), row-sum partials, pack P into A-frags ----
        u32 ah[8][4], al[8][4];
        #pragma unroll
        for (int t8 = 0; t8 < 8; t8++) {
            float eA0 = __expf(S[2*t8][0]),   eA1 = __expf(S[2*t8][1]);
            float eA2 = __expf(S[2*t8][2]),   eA3 = __expf(S[2*t8][3]);
            float eB0 = __expf(S[2*t8+1][0]), eB1 = __expf(S[2*t8+1][1]);
            float eB2 = __expf(S[2*t8+1][2]), eB3 = __expf(S[2*t8+1][3]);
            s0 += (eA0 + eA1) + (eB0 + eB1);
            s1 += (eA2 + eA3) + (eB2 + eB3);
            float hA0 = bfround(eA0), hA1 = bfround(eA1), hA2 = bfround(eA2), hA3 = bfround(eA3);
            float hB0 = bfround(eB0), hB1 = bfround(eB1), hB2 = bfround(eB2), hB3 = bfround(eB3);
            ah[t8][0] = pkbf2(hA0, hA1);  al[t8][0] = pkbf2(eA0-hA0, eA1-hA1);
            ah[t8][1] = pkbf2(hA2, hA3);  al[t8][1] = pkbf2(eA2-hA2, eA3-hA3);
            ah[t8][2] = pkbf2(hB0, hB1);  al[t8][2] = pkbf2(eB0-hB0, eB1-hB1);
            ah[t8][3] = pkbf2(hB2, hB3);  al[t8][3] = pkbf2(eB2-hB2, eB3-hB3);
        }

        // ---- GEMM2: O[16 x 64] += Ph*Vh + Ph*Vl + Pl*Vh ----
        #pragma unroll
        for (int nb = 0; nb < 8; nb++) {
            u32 base = sb + SV_H + (u32)((nb*8 + (lane&7))*272 + ((lane>>3)*16));
            u32 v0,v1,v2,v3,v4,v5,v6,v7,v8,v9,vA,vB,vC,vD,vE,vF;
            u32 w0,w1,w2,w3,w4,w5,w6,w7,w8,w9,wA,wB,wC,wD,wE,wF;
            LDSM4(v0,v1,v2,v3, base);
            LDSM4(v4,v5,v6,v7, base + 64);
            LDSM4(v8,v9,vA,vB, base + 128);
            LDSM4(vC,vD,vE,vF, base + 192);
            LDSM4(w0,w1,w2,w3, base + 17408);
            LDSM4(w4,w5,w6,w7, base + 17408 + 64);
            LDSM4(w8,w9,wA,wB, base + 17408 + 128);
            LDSM4(wC,wD,wE,wF, base + 17408 + 192);
            MMA(O[nb], ah[0][0],ah[0][1],ah[0][2],ah[0][3], v0,v1);
            MMA(O[nb], ah[1][0],ah[1][1],ah[1][2],ah[1][3], v2,v3);
            MMA(O[nb], ah[2][0],ah[2][1],ah[2][2],ah[2][3], v4,v5);
            MMA(O[nb], ah[3][0],ah[3][1],ah[3][2],ah[3][3], v6,v7);
            MMA(O[nb], ah[4][0],ah[4][1],ah[4][2],ah[4][3], v8,v9);
            MMA(O[nb], ah[5][0],ah[5][1],ah[5][2],ah[5][3], vA,vB);
            MMA(O[nb], ah[6][0],ah[6][1],ah[6][2],ah[6][3], vC,vD);
            MMA(O[nb], ah[7][0],ah[7][1],ah[7][2],ah[7][3], vE,vF);
            MMA(O[nb], ah[0][0],ah[0][1],ah[0][2],ah[0][3], w0,w1);
            MMA(O[nb], ah[1][0],ah[1][1],ah[1][2],ah[1][3], w2,w3);
            MMA(O[nb], ah[2][0],ah[2][1],ah[2][2],ah[2][3], w4,w5);
            MMA(O[nb], ah[3][0],ah[3][1],ah[3][2],ah[3][3], w6,w7);
            MMA(O[nb], ah[4][0],ah[4][1],ah[4][2],ah[4][3], w8,w9);
            MMA(O[nb], ah[5][0],ah[5][1],ah[5][2],ah[5][3], wA,wB);
            MMA(O[nb], ah[6][0],ah[6][1],ah[6][2],ah[6][3], wC,wD);
            MMA(O[nb], ah[7][0],ah[7][1],ah[7][2],ah[7][3], wE,wF);
            MMA(O[nb], al[0][0],al[0][1],al[0][2],al[0][3], v0,v1);
            MMA(O[nb], al[1][0],al[1][1],al[1][2],al[1][3], v2,v3);
            MMA(O[nb], al[2][0],al[2][1],al[2][2],al[2][3], v4,v5);
            MMA(O[nb], al[3][0],al[3][1],al[3][2],al[3][3], v6,v7);
            MMA(O[nb], al[4][0],al[4][1],al[4][2],al[4][3], v8,v9);
            MMA(O[nb], al[5][0],al[5][1],al[5][2],al[5][3], vA,vB);
            MMA(O[nb], al[6][0],al[6][1],al[6][2],al[6][3], vC,vD);
            MMA(O[nb], al[7][0],al[7][1],al[7][2],al[7][3], vE,vF);
        }
        __syncthreads();
    }

    // ---- final: reduce row sums within lane quad, normalize, residual write ----
    s0 += __shfl_xor_sync(0xffffffffu, s0, 1);
    s0 += __shfl_xor_sync(0xffffffffu, s0, 2);
    s1 += __shfl_xor_sync(0xffffffffu, s1, 1);
    s1 += __shfl_xor_sync(0xffffffffu, s1, 2);
    const float rl0 = 1.0f / s0, rl1 = 1.0f / s1;
    const float g = gamma[0];

    const int i  = ibase + i0 + (lane>>2);
    #pragma unroll
    for (int nb = 0; nb < 8; nb++) {
        int c = nb*8 + (lane&3)*2;
        size_t off = (size_t)b*CC*NN + (size_t)c*NN + i;
        out[off]        = g*(O[nb][0]*rl0) + x[off];
        out[off+NN]     = g*(O[nb][1]*rl0) + x[off+NN];
        out[off+8]      = g*(O[nb][2]*rl1) + x[off+8];
        out[off+NN+8]   = g*(O[nb][3]*rl1) + x[off+NN+8];
    }
}

// ---------------------------------------------------------------------------
extern "C" void kernel_launch(void* const* d_in, const int* in_sizes, int n_in,
                              void* d_out, int out_size)
{
    const float* x     = (const float*)d_in[0];
    const float* Wq    = (const float*)d_in[1];
    const float* bq    = (const float*)d_in[2];
    const float* Wk    = (const float*)d_in[3];
    const float* bk    = (const float*)d_in[4];
    const float* Wv    = (const float*)d_in[5];
    const float* bv    = (const float*)d_in[6];
    const float* gamma = (const float*)d_in[7];
    float* out = (float*)d_out;

    const int smem1 = (8192 + 3*64*68) * sizeof(float);  // 84,992 B
    const int smem2 = SMEM2;                             // 71,680 B -> 2 CTAs/SM

    cudaFuncSetAttribute(qkv_kernel,  cudaFuncAttributeMaxDynamicSharedMemorySize, smem1);
    cudaFuncSetAttribute(attn_kernel, cudaFuncAttributeMaxDynamicSharedMemorySize, smem2);

    qkv_kernel<<<dim3(32, 4), 256, smem1>>>(x, Wq, bq, Wk, bk, Wv, bv);
    attn_kernel<<<dim3(64, 4), 128, smem2>>>(x, gamma, out);
}

// round 10
// speedup vs baseline: 1.4369x; 1.4369x over previous
#include <cuda_runtime.h>
#include <cuda_bf16.h>
#include <math.h>

#define BB 4
#define CC 64
#define NN 4096
typedef unsigned int u32;

__device__ __nv_bfloat16 g_QTh[(size_t)BB*NN*CC];
__device__ __nv_bfloat16 g_QTl[(size_t)BB*NN*CC];
__device__ __nv_bfloat16 g_KTh[(size_t)BB*NN*CC];
__device__ __nv_bfloat16 g_KTl[(size_t)BB*NN*CC];
__device__ __nv_bfloat16 g_Vh [(size_t)BB*CC*NN];
__device__ __nv_bfloat16 g_Vl [(size_t)BB*CC*NN];

__device__ __forceinline__ u32 smem_u32(const void* p){
    u32 a; asm("{ .reg .u64 t; cvta.to.shared.u64 t, %1; cvt.u32.u64 %0, t; }":"=r"(a):"l"(p)); return a;
}
__device__ __forceinline__ u32 pkbf2(float e0, float e1){     // lo=e0, hi=e1
    u32 r; asm("cvt.rn.bf16x2.f32 %0, %1, %2;" : "=r"(r) : "f"(e1), "f"(e0)); return r;
}
__device__ __forceinline__ float bfround(float a){
    return __bfloat162float(__float2bfloat16_rn(a));
}
#define LDSM4(r0,r1,r2,r3,addr) \
    asm volatile("ldmatrix.sync.aligned.m8n8.x4.shared.b16 {%0,%1,%2,%3},[%4];" \
        : "=r"(r0),"=r"(r1),"=r"(r2),"=r"(r3) : "r"(addr))
#define MMA(d,a0,a1,a2,a3,b0,b1) \
    asm volatile("mma.sync.aligned.m16n8k16.row.col.f32.bf16.bf16.f32 " \
        "{%0,%1,%2,%3},{%4,%5,%6,%7},{%8,%9},{%0,%1,%2,%3};" \
        : "+f"((d)[0]),"+f"((d)[1]),"+f"((d)[2]),"+f"((d)[3]) \
        : "r"(a0),"r"(a1),"r"(a2),"r"(a3),"r"(b0),"r"(b1))
#define CPA(dst,src) \
    asm volatile("cp.async.ca.shared.global [%0],[%1],16;"::"r"(dst),"l"(src))
#define CPA_COMMIT() asm volatile("cp.async.commit_group;":::"memory")
#define CPA_WAIT0()  asm volatile("cp.async.wait_group 0;":::"memory")

__device__ __forceinline__ void split2(float a0, float a1, u32& hi, u32& lo){
    float h0 = bfround(a0), h1 = bfround(a1);
    hi = pkbf2(h0, h1);
    lo = pkbf2(a0 - h0, a1 - h1);
}

// per-buffer smem offsets: K rows 144B stride, V rows 272B stride
#define SK_H 0
#define SK_L 18432
#define SV_H 36864
#define SV_L 54272
#define BUFSZ 71680
#define SMEM2 (2*BUFSZ)   // 143,360 B

// ------------------- Kernel 1: QKV + bf16 hi/lo split -------------------
__global__ void __launch_bounds__(256) qkv_kernel(
    const float* __restrict__ x,
    const float* __restrict__ Wq, const float* __restrict__ bq,
    const float* __restrict__ Wk, const float* __restrict__ bk,
    const float* __restrict__ Wv, const float* __restrict__ bv)
{
    extern __shared__ float sm1[];
    float* xs  = sm1;            // [64][128] then staging [128][64]
    float* wtq = sm1 + 8192;
    float* wtk = wtq + 64*68;
    float* wtv = wtk + 64*68;
    const int t = threadIdx.x, b = blockIdx.y, nbase = blockIdx.x*128;

    for (int idx = t; idx < 64*64; idx += 256) {
        int o = idx>>6, c = idx&63;
        wtq[c*68+o]=Wq[idx]; wtk[c*68+o]=Wk[idx]; wtv[c*68+o]=Wv[idx];
    }
    const float* xb = x + (size_t)b*CC*NN + nbase;
    for (int i4 = t; i4 < 2048; i4 += 256) {
        int c = i4>>5, n4 = (i4&31)<<2;
        *(float4*)&xs[c*128+n4] = *(const float4*)&xb[(size_t)c*NN+n4];
    }
    __syncthreads();
    const int ty = t>>4, tx = t&15, o0 = ty*4, n0 = tx*8;
    float aq[4][8], ak[4][8], av[4][8];
    #pragma unroll
    for (int r = 0; r < 4; r++) {
        float vq=bq[o0+r], vk=bk[o0+r], vv=bv[o0+r];
        #pragma unroll
        for (int s = 0; s < 8; s++){ aq[r][s]=vq; ak[r][s]=vk; av[r][s]=vv; }
    }
    #pragma unroll 4
    for (int c = 0; c < 64; c++) {
        float wqa[4],wka[4],wva[4],xr[8];
        *(float4*)&wqa[0]=*(float4*)&wtq[c*68+o0];
        *(float4*)&wka[0]=*(float4*)&wtk[c*68+o0];
        *(float4*)&wva[0]=*(float4*)&wtv[c*68+o0];
        *(float4*)&xr[0]=*(float4*)&xs[c*128+n0];
        *(float4*)&xr[4]=*(float4*)&xs[c*128+n0+4];
        #pragma unroll
        for (int r = 0; r < 4; r++)
            #pragma unroll
            for (int s = 0; s < 8; s++){
                aq[r][s]+=wqa[r]*xr[s]; ak[r][s]+=wka[r]*xr[s]; av[r][s]+=wva[r]*xr[s];
            }
    }
    // V: natural [c][n]
    #pragma unroll
    for (int r = 0; r < 4; r++) {
        size_t off = (size_t)b*CC*NN + (size_t)(o0+r)*NN + nbase + n0;
        #pragma unroll
        for (int m = 0; m < 4; m++) {
            u32 hi, lo; split2(av[r][2*m], av[r][2*m+1], hi, lo);
            *(u32*)(g_Vh+off+2*m) = hi; *(u32*)(g_Vl+off+2*m) = lo;
        }
    }
    // Q transposed [n][c]
    __syncthreads();
    #pragma unroll
    for (int r = 0; r < 4; r++)
        #pragma unroll
        for (int s = 0; s < 8; s++) xs[(n0+s)*64+o0+r] = aq[r][s];
    __syncthreads();
    {
        int n = t>>1, cb = (t&1)*32;
        const float* src = &xs[n*64+cb];
        size_t gb = ((size_t)b*NN + nbase + n)*CC + cb;
        #pragma unroll
        for (int m = 0; m < 16; m++) {
            u32 hi, lo; split2(src[2*m], src[2*m+1], hi, lo);
            *(u32*)(g_QTh+gb+2*m) = hi; *(u32*)(g_QTl+gb+2*m) = lo;
        }
    }
    __syncthreads();
    #pragma unroll
    for (int r = 0; r < 4; r++)
        #pragma unroll
        for (int s = 0; s < 8; s++) xs[(n0+s)*64+o0+r] = ak[r][s];
    __syncthreads();
    {
        int n = t>>1, cb = (t&1)*32;
        const float* src = &xs[n*64+cb];
        size_t gb = ((size_t)b*NN + nbase + n)*CC + cb;
        #pragma unroll
        for (int m = 0; m < 16; m++) {
            u32 hi, lo; split2(src[2*m], src[2*m+1], hi, lo);
            *(u32*)(g_KTh+gb+2*m) = hi; *(u32*)(g_KTl+gb+2*m) = lo;
        }
    }
}

// prefetch one K/V tile (hi+lo) into smem buffer via cp.async
__device__ __forceinline__ void prefetch_tile(
    char* smbuf,
    const __nv_bfloat16* kh, const __nv_bfloat16* kl,
    const __nv_bfloat16* vh, const __nv_bfloat16* vl,
    int jt, int t)
{
    const u32 sbuf = smem_u32(smbuf);
    #pragma unroll
    for (int k = 0; k < 4; k++) {
        int idx = t + k*256, row = idx>>3, ch = idx&7;
        CPA(sbuf + SK_H + row*144 + ch*16, (const char*)(kh + (size_t)(jt+row)*CC) + ch*16);
        CPA(sbuf + SK_L + row*144 + ch*16, (const char*)(kl + (size_t)(jt+row)*CC) + ch*16);
    }
    #pragma unroll
    for (int k = 0; k < 4; k++) {
        int idx = t + k*256, row = idx>>4, ch = idx&15;
        CPA(sbuf + SV_H + row*272 + ch*16, (const char*)(vh + (size_t)row*NN + jt) + ch*16);
        CPA(sbuf + SV_L + row*272 + ch*16, (const char*)(vl + (size_t)row*NN + jt) + ch*16);
    }
}

// ------------------- Kernel 2: HMMA flash attention, cp.async pipelined -------------------
// 128 q-rows/CTA, 8 warps (warp owns 16 rows), grid (32,4), double-buffered K/V.
__global__ void __launch_bounds__(256) attn_kernel(
    const float* __restrict__ x, const float* __restrict__ gamma,
    float* __restrict__ out)
{
    extern __shared__ __align__(16) char sm2[];
    const int t = threadIdx.x, wid = t>>5, lane = t&31;
    const int i0 = wid*16;
    const int b = blockIdx.y, ibase = blockIdx.x*128;

    const __nv_bfloat16* qh = g_QTh + (size_t)b*NN*CC;
    const __nv_bfloat16* ql = g_QTl + (size_t)b*NN*CC;
    const __nv_bfloat16* kh = g_KTh + (size_t)b*NN*CC;
    const __nv_bfloat16* kl = g_KTl + (size_t)b*NN*CC;
    const __nv_bfloat16* vh = g_Vh  + (size_t)b*CC*NN;
    const __nv_bfloat16* vl = g_Vl  + (size_t)b*CC*NN;

    // prefetch tile 0 -> buf0; stage Q -> buf1 K area (also via cp.async)
    prefetch_tile(sm2, kh, kl, vh, vl, 0, t);
    {
        const u32 sq = smem_u32(sm2 + BUFSZ);
        #pragma unroll
        for (int k = 0; k < 4; k++) {
            int idx = t + k*256, row = idx>>3, ch = idx&7;
            CPA(sq + SK_H + row*144 + ch*16, (const char*)(qh + (size_t)(ibase+row)*CC) + ch*16);
            CPA(sq + SK_L + row*144 + ch*16, (const char*)(ql + (size_t)(ibase+row)*CC) + ch*16);
        }
    }
    CPA_COMMIT();
    CPA_WAIT0();
    __syncthreads();

    u32 qfh[4][4], qfl[4][4];
    {
        u32 abase = smem_u32(sm2 + BUFSZ) + (u32)((i0 + (lane&15))*144 + ((lane>>4)*16));
        #pragma unroll
        for (int ks = 0; ks < 4; ks++) {
            LDSM4(qfh[ks][0],qfh[ks][1],qfh[ks][2],qfh[ks][3], abase + ks*32);
            LDSM4(qfl[ks][0],qfl[ks][1],qfl[ks][2],qfl[ks][3], abase + ks*32 + 18432);
        }
    }
    __syncthreads();     // all warps done reading Q staging before buf1 is reused

    float O[8][4];
    #pragma unroll
    for (int nb = 0; nb < 8; nb++)
        #pragma unroll
        for (int k = 0; k < 4; k++) O[nb][k] = 0.f;
    float s0 = 0.f, s1 = 0.f;

    for (int tile = 0; tile < 32; tile++) {
        char* cur = sm2 + (tile & 1)*BUFSZ;
        char* nxt = sm2 + ((tile & 1)^1)*BUFSZ;
        if (tile > 0) { CPA_WAIT0(); __syncthreads(); }
        if (tile < 31) { prefetch_tile(nxt, kh, kl, vh, vl, (tile+1)<<7, t); CPA_COMMIT(); }

        const u32 sb = smem_u32(cur);

        // ---- GEMM1: S[16 x 128] = Qh*Kh + Qh*Kl + Ql*Kh ----
        float S[16][4];
        #pragma unroll
        for (int nb = 0; nb < 16; nb++) {
            #pragma unroll
            for (int k = 0; k < 4; k++) S[nb][k] = 0.f;
            u32 base = sb + SK_H + (u32)((nb*8 + (lane&7))*144 + ((lane>>3)*16));
            u32 h0,h1,h2,h3,h4,h5,h6,h7, l0,l1,l2,l3,l4,l5,l6,l7;
            LDSM4(h0,h1,h2,h3, base);
            LDSM4(h4,h5,h6,h7, base + 64);
            LDSM4(l0,l1,l2,l3, base + 18432);
            LDSM4(l4,l5,l6,l7, base + 18432 + 64);
            MMA(S[nb], qfh[0][0],qfh[0][1],qfh[0][2],qfh[0][3], h0,h1);
            MMA(S[nb], qfh[1][0],qfh[1][1],qfh[1][2],qfh[1][3], h2,h3);
            MMA(S[nb], qfh[2][0],qfh[2][1],qfh[2][2],qfh[2][3], h4,h5);
            MMA(S[nb], qfh[3][0],qfh[3][1],qfh[3][2],qfh[3][3], h6,h7);
            MMA(S[nb], qfh[0][0],qfh[0][1],qfh[0][2],qfh[0][3], l0,l1);
            MMA(S[nb], qfh[1][0],qfh[1][1],qfh[1][2],qfh[1][3], l2,l3);
            MMA(S[nb], qfh[2][0],qfh[2][1],qfh[2][2],qfh[2][3], l4,l5);
            MMA(S[nb], qfh[3][0],qfh[3][1],qfh[3][2],qfh[3][3], l6,l7);
            MMA(S[nb], qfl[0][0],qfl[0][1],qfl[0][2],qfl[0][3], h0,h1);
            MMA(S[nb], qfl[1][0],qfl[1][1],qfl[1][2],qfl[1][3], h2,h3);
            MMA(S[nb], qfl[2][0],qfl[2][1],qfl[2][2],qfl[2][3], h4,h5);
            MMA(S[nb], qfl[3][0],qfl[3][1],qfl[3][2],qfl[3][3], h6,h7);
        }

        // ---- exp (unnormalized), row-sum partials, pack P (hi only) ----
        u32 ah[8][4];
        #pragma unroll
        for (int t8 = 0; t8 < 8; t8++) {
            float eA0 = __expf(S[2*t8][0]),   eA1 = __expf(S[2*t8][1]);
            float eA2 = __expf(S[2*t8][2]),   eA3 = __expf(S[2*t8][3]);
            float eB0 = __expf(S[2*t8+1][0]), eB1 = __expf(S[2*t8+1][1]);
            float eB2 = __expf(S[2*t8+1][2]), eB3 = __expf(S[2*t8+1][3]);
            s0 += (eA0 + eA1) + (eB0 + eB1);
            s1 += (eA2 + eA3) + (eB2 + eB3);
            ah[t8][0] = pkbf2(eA0, eA1);
            ah[t8][1] = pkbf2(eA2, eA3);
            ah[t8][2] = pkbf2(eB0, eB1);
            ah[t8][3] = pkbf2(eB2, eB3);
        }

        // ---- GEMM2: O[16 x 64] += Ph*Vh + Ph*Vl ----
        #pragma unroll
        for (int nb = 0; nb < 8; nb++) {
            u32 base = sb + SV_H + (u32)((nb*8 + (lane&7))*272 + ((lane>>3)*16));
            u32 v0,v1,v2,v3,v4,v5,v6,v7,v8,v9,vA,vB,vC,vD,vE,vF;
            u32 w0,w1,w2,w3,w4,w5,w6,w7,w8,w9,wA,wB,wC,wD,wE,wF;
            LDSM4(v0,v1,v2,v3, base);
            LDSM4(v4,v5,v6,v7, base + 64);
            LDSM4(v8,v9,vA,vB, base + 128);
            LDSM4(vC,vD,vE,vF, base + 192);
            LDSM4(w0,w1,w2,w3, base + 17408);
            LDSM4(w4,w5,w6,w7, base + 17408 + 64);
            LDSM4(w8,w9,wA,wB, base + 17408 + 128);
            LDSM4(wC,wD,wE,wF, base + 17408 + 192);
            MMA(O[nb], ah[0][0],ah[0][1],ah[0][2],ah[0][3], v0,v1);
            MMA(O[nb], ah[1][0],ah[1][1],ah[1][2],ah[1][3], v2,v3);
            MMA(O[nb], ah[2][0],ah[2][1],ah[2][2],ah[2][3], v4,v5);
            MMA(O[nb], ah[3][0],ah[3][1],ah[3][2],ah[3][3], v6,v7);
            MMA(O[nb], ah[4][0],ah[4][1],ah[4][2],ah[4][3], v8,v9);
            MMA(O[nb], ah[5][0],ah[5][1],ah[5][2],ah[5][3], vA,vB);
            MMA(O[nb], ah[6][0],ah[6][1],ah[6][2],ah[6][3], vC,vD);
            MMA(O[nb], ah[7][0],ah[7][1],ah[7][2],ah[7][3], vE,vF);
            MMA(O[nb], ah[0][0],ah[0][1],ah[0][2],ah[0][3], w0,w1);
            MMA(O[nb], ah[1][0],ah[1][1],ah[1][2],ah[1][3], w2,w3);
            MMA(O[nb], ah[2][0],ah[2][1],ah[2][2],ah[2][3], w4,w5);
            MMA(O[nb], ah[3][0],ah[3][1],ah[3][2],ah[3][3], w6,w7);
            MMA(O[nb], ah[4][0],ah[4][1],ah[4][2],ah[4][3], w8,w9);
            MMA(O[nb], ah[5][0],ah[5][1],ah[5][2],ah[5][3], wA,wB);
            MMA(O[nb], ah[6][0],ah[6][1],ah[6][2],ah[6][3], wC,wD);
            MMA(O[nb], ah[7][0],ah[7][1],ah[7][2],ah[7][3], wE,wF);
        }
    }

    // ---- final: reduce row sums within lane quad, normalize, residual write ----
    s0 += __shfl_xor_sync(0xffffffffu, s0, 1);
    s0 += __shfl_xor_sync(0xffffffffu, s0, 2);
    s1 += __shfl_xor_sync(0xffffffffu, s1, 1);
    s1 += __shfl_xor_sync(0xffffffffu, s1, 2);
    const float rl0 = 1.0f / s0, rl1 = 1.0f / s1;
    const float g = gamma[0];

    const int i  = ibase + i0 + (lane>>2);
    #pragma unroll
    for (int nb = 0; nb < 8; nb++) {
        int c = nb*8 + (lane&3)*2;
        size_t off = (size_t)b*CC*NN + (size_t)c*NN + i;
        out[off]        = g*(O[nb][0]*rl0) + x[off];
        out[off+NN]     = g*(O[nb][1]*rl0) + x[off+NN];
        out[off+8]      = g*(O[nb][2]*rl1) + x[off+8];
        out[off+NN+8]   = g*(O[nb][3]*rl1) + x[off+NN+8];
    }
}

// ---------------------------------------------------------------------------
extern "C" void kernel_launch(void* const* d_in, const int* in_sizes, int n_in,
                              void* d_out, int out_size)
{
    const float* x     = (const float*)d_in[0];
    const float* Wq    = (const float*)d_in[1];
    const float* bq    = (const float*)d_in[2];
    const float* Wk    = (const float*)d_in[3];
    const float* bk    = (const float*)d_in[4];
    const float* Wv    = (const float*)d_in[5];
    const float* bv    = (const float*)d_in[6];
    const float* gamma = (const float*)d_in[7];
    float* out = (float*)d_out;

    const int smem1 = (8192 + 3*64*68) * sizeof(float);  // 84,992 B
    const int smem2 = SMEM2;                             // 143,360 B

    cudaFuncSetAttribute(qkv_kernel,  cudaFuncAttributeMaxDynamicSharedMemorySize, smem1);
    cudaFuncSetAttribute(attn_kernel, cudaFuncAttributeMaxDynamicSharedMemorySize, smem2);

    qkv_kernel<<<dim3(32, 4), 256, smem1>>>(x, Wq, bq, Wk, bk, Wv, bv);
    attn_kernel<<<dim3(32, 4), 256, smem2>>>(x, gamma, out);
}

// round 11
// speedup vs baseline: 1.4808x; 1.0305x over previous
#include <cuda_runtime.h>
#include <cuda_bf16.h>
#include <math.h>

#define BB 4
#define CC 64
#define NN 4096
#define LOG2E 1.4426950408889634f
typedef unsigned int u32;

__device__ __nv_bfloat16 g_QTh[(size_t)BB*NN*CC];
__device__ __nv_bfloat16 g_QTl[(size_t)BB*NN*CC];
__device__ __nv_bfloat16 g_KTh[(size_t)BB*NN*CC];
__device__ __nv_bfloat16 g_KTl[(size_t)BB*NN*CC];
__device__ __nv_bfloat16 g_Vh [(size_t)BB*CC*NN];
__device__ __nv_bfloat16 g_Vl [(size_t)BB*CC*NN];

__device__ __forceinline__ u32 smem_u32(const void* p){
    u32 a; asm("{ .reg .u64 t; cvta.to.shared.u64 t, %1; cvt.u32.u64 %0, t; }":"=r"(a):"l"(p)); return a;
}
__device__ __forceinline__ u32 pkbf2(float e0, float e1){     // lo=e0, hi=e1
    u32 r; asm("cvt.rn.bf16x2.f32 %0, %1, %2;" : "=r"(r) : "f"(e1), "f"(e0)); return r;
}
__device__ __forceinline__ float bfround(float a){
    return __bfloat162float(__float2bfloat16_rn(a));
}
__device__ __forceinline__ float ex2f(float x){
    float r; asm("ex2.approx.f32 %0,%1;" : "=f"(r) : "f"(x)); return r;
}
#define LDSM4(r0,r1,r2,r3,addr) \
    asm volatile("ldmatrix.sync.aligned.m8n8.x4.shared.b16 {%0,%1,%2,%3},[%4];" \
        : "=r"(r0),"=r"(r1),"=r"(r2),"=r"(r3) : "r"(addr))
#define MMA(d,a0,a1,a2,a3,b0,b1) \
    asm volatile("mma.sync.aligned.m16n8k16.row.col.f32.bf16.bf16.f32 " \
        "{%0,%1,%2,%3},{%4,%5,%6,%7},{%8,%9},{%0,%1,%2,%3};" \
        : "+f"((d)[0]),"+f"((d)[1]),"+f"((d)[2]),"+f"((d)[3]) \
        : "r"(a0),"r"(a1),"r"(a2),"r"(a3),"r"(b0),"r"(b1))
#define CPA(dst,src) \
    asm volatile("cp.async.ca.shared.global [%0],[%1],16;"::"r"(dst),"l"(src))
#define CPA_COMMIT() asm volatile("cp.async.commit_group;":::"memory")
#define CPA_WAIT0()  asm volatile("cp.async.wait_group 0;":::"memory")

__device__ __forceinline__ void split2(float a0, float a1, u32& hi, u32& lo){
    float h0 = bfround(a0), h1 = bfround(a1);
    hi = pkbf2(h0, h1);
    lo = pkbf2(a0 - h0, a1 - h1);
}

// per-buffer smem offsets: K rows 144B stride, V rows 272B stride
#define SK_H 0
#define SK_L 18432
#define SV_H 36864
#define SV_L 54272
#define BUFSZ 71680
#define SMEM2 (2*BUFSZ)   // 143,360 B

// ------------------- Kernel 1: QKV + bf16 hi/lo split -------------------
__global__ void __launch_bounds__(256) qkv_kernel(
    const float* __restrict__ x,
    const float* __restrict__ Wq, const float* __restrict__ bq,
    const float* __restrict__ Wk, const float* __restrict__ bk,
    const float* __restrict__ Wv, const float* __restrict__ bv)
{
    extern __shared__ float sm1[];
    float* xs  = sm1;            // [64][128] then staging [128][64]
    float* wtq = sm1 + 8192;
    float* wtk = wtq + 64*68;
    float* wtv = wtk + 64*68;
    const int t = threadIdx.x, b = blockIdx.y, nbase = blockIdx.x*128;

    for (int idx = t; idx < 64*64; idx += 256) {
        int o = idx>>6, c = idx&63;
        wtq[c*68+o]=Wq[idx]; wtk[c*68+o]=Wk[idx]; wtv[c*68+o]=Wv[idx];
    }
    const float* xb = x + (size_t)b*CC*NN + nbase;
    for (int i4 = t; i4 < 2048; i4 += 256) {
        int c = i4>>5, n4 = (i4&31)<<2;
        *(float4*)&xs[c*128+n4] = *(const float4*)&xb[(size_t)c*NN+n4];
    }
    __syncthreads();
    const int ty = t>>4, tx = t&15, o0 = ty*4, n0 = tx*8;
    float aq[4][8], ak[4][8], av[4][8];
    #pragma unroll
    for (int r = 0; r < 4; r++) {
        float vq=bq[o0+r], vk=bk[o0+r], vv=bv[o0+r];
        #pragma unroll
        for (int s = 0; s < 8; s++){ aq[r][s]=vq; ak[r][s]=vk; av[r][s]=vv; }
    }
    #pragma unroll 4
    for (int c = 0; c < 64; c++) {
        float wqa[4],wka[4],wva[4],xr[8];
        *(float4*)&wqa[0]=*(float4*)&wtq[c*68+o0];
        *(float4*)&wka[0]=*(float4*)&wtk[c*68+o0];
        *(float4*)&wva[0]=*(float4*)&wtv[c*68+o0];
        *(float4*)&xr[0]=*(float4*)&xs[c*128+n0];
        *(float4*)&xr[4]=*(float4*)&xs[c*128+n0+4];
        #pragma unroll
        for (int r = 0; r < 4; r++)
            #pragma unroll
            for (int s = 0; s < 8; s++){
                aq[r][s]+=wqa[r]*xr[s]; ak[r][s]+=wka[r]*xr[s]; av[r][s]+=wva[r]*xr[s];
            }
    }
    // V: natural [c][n]
    #pragma unroll
    for (int r = 0; r < 4; r++) {
        size_t off = (size_t)b*CC*NN + (size_t)(o0+r)*NN + nbase + n0;
        #pragma unroll
        for (int m = 0; m < 4; m++) {
            u32 hi, lo; split2(av[r][2*m], av[r][2*m+1], hi, lo);
            *(u32*)(g_Vh+off+2*m) = hi; *(u32*)(g_Vl+off+2*m) = lo;
        }
    }
    // Q transposed [n][c], pre-scaled by log2(e) so softmax uses raw ex2
    __syncthreads();
    #pragma unroll
    for (int r = 0; r < 4; r++)
        #pragma unroll
        for (int s = 0; s < 8; s++) xs[(n0+s)*64+o0+r] = aq[r][s]*LOG2E;
    __syncthreads();
    {
        int n = t>>1, cb = (t&1)*32;
        const float* src = &xs[n*64+cb];
        size_t gb = ((size_t)b*NN + nbase + n)*CC + cb;
        #pragma unroll
        for (int m = 0; m < 16; m++) {
            u32 hi, lo; split2(src[2*m], src[2*m+1], hi, lo);
            *(u32*)(g_QTh+gb+2*m) = hi; *(u32*)(g_QTl+gb+2*m) = lo;
        }
    }
    __syncthreads();
    #pragma unroll
    for (int r = 0; r < 4; r++)
        #pragma unroll
        for (int s = 0; s < 8; s++) xs[(n0+s)*64+o0+r] = ak[r][s];
    __syncthreads();
    {
        int n = t>>1, cb = (t&1)*32;
        const float* src = &xs[n*64+cb];
        size_t gb = ((size_t)b*NN + nbase + n)*CC + cb;
        #pragma unroll
        for (int m = 0; m < 16; m++) {
            u32 hi, lo; split2(src[2*m], src[2*m+1], hi, lo);
            *(u32*)(g_KTh+gb+2*m) = hi; *(u32*)(g_KTl+gb+2*m) = lo;
        }
    }
}

// prefetch one K/V tile (hi+lo) into smem buffer via cp.async
__device__ __forceinline__ void prefetch_tile(
    char* smbuf,
    const __nv_bfloat16* kh, const __nv_bfloat16* kl,
    const __nv_bfloat16* vh, const __nv_bfloat16* vl,
    int jt, int t)
{
    const u32 sbuf = smem_u32(smbuf);
    #pragma unroll
    for (int k = 0; k < 4; k++) {
        int idx = t + k*256, row = idx>>3, ch = idx&7;
        CPA(sbuf + SK_H + row*144 + ch*16, (const char*)(kh + (size_t)(jt+row)*CC) + ch*16);
        CPA(sbuf + SK_L + row*144 + ch*16, (const char*)(kl + (size_t)(jt+row)*CC) + ch*16);
    }
    #pragma unroll
    for (int k = 0; k < 4; k++) {
        int idx = t + k*256, row = idx>>4, ch = idx&15;
        CPA(sbuf + SV_H + row*272 + ch*16, (const char*)(vh + (size_t)row*NN + jt) + ch*16);
        CPA(sbuf + SV_L + row*272 + ch*16, (const char*)(vl + (size_t)row*NN + jt) + ch*16);
    }
}

// ------------------- Kernel 2: HMMA flash attention, j-split warps -------------------
// 128 q-rows/CTA, 8 warps: warp = 32 q-rows x 64 j-cols (rg = wid&3, jh = wid>>2).
// Each warp reads only half of K and half of V per tile. O j-half partials and
// row sums are combined once in the epilogue via smem.
__global__ void __launch_bounds__(256) attn_kernel(
    const float* __restrict__ x, const float* __restrict__ gamma,
    float* __restrict__ out)
{
    extern __shared__ __align__(16) char sm2[];
    const int t = threadIdx.x, wid = t>>5, lane = t&31;
    const int rg = wid & 3, jh = wid >> 2;
    const int i0 = rg*32;            // warp's 32 query rows
    const int jcol0 = jh*64;         // warp's 64 key cols within tile
    const int b = blockIdx.y, ibase = blockIdx.x*128;

    const __nv_bfloat16* qh = g_QTh + (size_t)b*NN*CC;
    const __nv_bfloat16* ql = g_QTl + (size_t)b*NN*CC;
    const __nv_bfloat16* kh = g_KTh + (size_t)b*NN*CC;
    const __nv_bfloat16* kl = g_KTl + (size_t)b*NN*CC;
    const __nv_bfloat16* vh = g_Vh  + (size_t)b*CC*NN;
    const __nv_bfloat16* vl = g_Vl  + (size_t)b*CC*NN;

    // prefetch tile 0 -> buf0; stage Q -> buf1 K area
    prefetch_tile(sm2, kh, kl, vh, vl, 0, t);
    {
        const u32 sq = smem_u32(sm2 + BUFSZ);
        #pragma unroll
        for (int k = 0; k < 4; k++) {
            int idx = t + k*256, row = idx>>3, ch = idx&7;
            CPA(sq + SK_H + row*144 + ch*16, (const char*)(qh + (size_t)(ibase+row)*CC) + ch*16);
            CPA(sq + SK_L + row*144 + ch*16, (const char*)(ql + (size_t)(ibase+row)*CC) + ch*16);
        }
    }
    CPA_COMMIT();
    CPA_WAIT0();
    __syncthreads();

    // Q A-frags for the warp's two m16 blocks
    u32 qfh[2][4][4], qfl[2][4][4];
    #pragma unroll
    for (int mb = 0; mb < 2; mb++) {
        u32 abase = smem_u32(sm2 + BUFSZ) + (u32)((i0 + mb*16 + (lane&15))*144 + ((lane>>4)*16));
        #pragma unroll
        for (int ks = 0; ks < 4; ks++) {
            LDSM4(qfh[mb][ks][0],qfh[mb][ks][1],qfh[mb][ks][2],qfh[mb][ks][3], abase + ks*32);
            LDSM4(qfl[mb][ks][0],qfl[mb][ks][1],qfl[mb][ks][2],qfl[mb][ks][3], abase + ks*32 + 18432);
        }
    }
    __syncthreads();   // Q staging (buf1) free for tile-1 prefetch

    float O[2][8][4];
    #pragma unroll
    for (int mb = 0; mb < 2; mb++)
        #pragma unroll
        for (int nb = 0; nb < 8; nb++)
            #pragma unroll
            for (int k = 0; k < 4; k++) O[mb][nb][k] = 0.f;
    float srow[2][2] = {{0.f,0.f},{0.f,0.f}};   // [mb][r / r+8] partial sums

    for (int tile = 0; tile < 32; tile++) {
        char* cur = sm2 + (tile & 1)*BUFSZ;
        char* nxt = sm2 + ((tile & 1)^1)*BUFSZ;
        if (tile > 0) { CPA_WAIT0(); __syncthreads(); }
        if (tile < 31) { prefetch_tile(nxt, kh, kl, vh, vl, (tile+1)<<7, t); CPA_COMMIT(); }

        const u32 sb = smem_u32(cur);

        // ---- GEMM1: S[32 x 64] = Qh*Kh + Qh*Kl + Ql*Kh (K frags shared over mb) ----
        float S[2][8][4];
        #pragma unroll
        for (int nb = 0; nb < 8; nb++) {
            u32 base = sb + SK_H + (u32)(((jcol0 + nb*8 + (lane&7))*144) + ((lane>>3)*16));
            u32 h0,h1,h2,h3,h4,h5,h6,h7, l0,l1,l2,l3,l4,l5,l6,l7;
            LDSM4(h0,h1,h2,h3, base);
            LDSM4(h4,h5,h6,h7, base + 64);
            LDSM4(l0,l1,l2,l3, base + 18432);
            LDSM4(l4,l5,l6,l7, base + 18432 + 64);
            #pragma unroll
            for (int mb = 0; mb < 2; mb++) {
                float* D = S[mb][nb];
                D[0]=D[1]=D[2]=D[3]=0.f;
                MMA(D, qfh[mb][0][0],qfh[mb][0][1],qfh[mb][0][2],qfh[mb][0][3], h0,h1);
                MMA(D, qfh[mb][1][0],qfh[mb][1][1],qfh[mb][1][2],qfh[mb][1][3], h2,h3);
                MMA(D, qfh[mb][2][0],qfh[mb][2][1],qfh[mb][2][2],qfh[mb][2][3], h4,h5);
                MMA(D, qfh[mb][3][0],qfh[mb][3][1],qfh[mb][3][2],qfh[mb][3][3], h6,h7);
                MMA(D, qfh[mb][0][0],qfh[mb][0][1],qfh[mb][0][2],qfh[mb][0][3], l0,l1);
                MMA(D, qfh[mb][1][0],qfh[mb][1][1],qfh[mb][1][2],qfh[mb][1][3], l2,l3);
                MMA(D, qfh[mb][2][0],qfh[mb][2][1],qfh[mb][2][2],qfh[mb][2][3], l4,l5);
                MMA(D, qfh[mb][3][0],qfh[mb][3][1],qfh[mb][3][2],qfh[mb][3][3], l6,l7);
                MMA(D, qfl[mb][0][0],qfl[mb][0][1],qfl[mb][0][2],qfl[mb][0][3], h0,h1);
                MMA(D, qfl[mb][1][0],qfl[mb][1][1],qfl[mb][1][2],qfl[mb][1][3], h2,h3);
                MMA(D, qfl[mb][2][0],qfl[mb][2][1],qfl[mb][2][2],qfl[mb][2][3], h4,h5);
                MMA(D, qfl[mb][3][0],qfl[mb][3][1],qfl[mb][3][2],qfl[mb][3][3], h6,h7);
            }
        }

        // ---- exp2 (Q pre-scaled by log2e), row-sum partials, pack P A-frags ----
        u32 ah[2][4][4];
        #pragma unroll
        for (int mb = 0; mb < 2; mb++) {
            #pragma unroll
            for (int ks = 0; ks < 4; ks++) {
                const float* SA = S[mb][2*ks];
                const float* SB = S[mb][2*ks+1];
                float eA0 = ex2f(SA[0]), eA1 = ex2f(SA[1]);
                float eA2 = ex2f(SA[2]), eA3 = ex2f(SA[3]);
                float eB0 = ex2f(SB[0]), eB1 = ex2f(SB[1]);
                float eB2 = ex2f(SB[2]), eB3 = ex2f(SB[3]);
                srow[mb][0] += (eA0 + eA1) + (eB0 + eB1);
                srow[mb][1] += (eA2 + eA3) + (eB2 + eB3);
                ah[mb][ks][0] = pkbf2(eA0, eA1);
                ah[mb][ks][1] = pkbf2(eA2, eA3);
                ah[mb][ks][2] = pkbf2(eB0, eB1);
                ah[mb][ks][3] = pkbf2(eB2, eB3);
            }
        }

        // ---- GEMM2: O[32 x 64] += Ph*Vh + Ph*Vl over this warp's j-half ----
        #pragma unroll
        for (int nb = 0; nb < 8; nb++) {
            u32 base = sb + SV_H + (u32)((nb*8 + (lane&7))*272 + jcol0*2 + ((lane>>3)*16));
            u32 v0,v1,v2,v3,v4,v5,v6,v7;
            u32 w0,w1,w2,w3,w4,w5,w6,w7;
            LDSM4(v0,v1,v2,v3, base);
            LDSM4(v4,v5,v6,v7, base + 64);
            LDSM4(w0,w1,w2,w3, base + 17408);
            LDSM4(w4,w5,w6,w7, base + 17408 + 64);
            #pragma unroll
            for (int mb = 0; mb < 2; mb++) {
                float* D = O[mb][nb];
                MMA(D, ah[mb][0][0],ah[mb][0][1],ah[mb][0][2],ah[mb][0][3], v0,v1);
                MMA(D, ah[mb][1][0],ah[mb][1][1],ah[mb][1][2],ah[mb][1][3], v2,v3);
                MMA(D, ah[mb][2][0],ah[mb][2][1],ah[mb][2][2],ah[mb][2][3], v4,v5);
                MMA(D, ah[mb][3][0],ah[mb][3][1],ah[mb][3][2],ah[mb][3][3], v6,v7);
                MMA(D, ah[mb][0][0],ah[mb][0][1],ah[mb][0][2],ah[mb][0][3], w0,w1);
                MMA(D, ah[mb][1][0],ah[mb][1][1],ah[mb][1][2],ah[mb][1][3], w2,w3);
                MMA(D, ah[mb][2][0],ah[mb][2][1],ah[mb][2][2],ah[mb][2][3], w4,w5);
                MMA(D, ah[mb][3][0],ah[mb][3][1],ah[mb][3][2],ah[mb][3][3], w6,w7);
            }
        }
    }

    // ---- epilogue: combine j-halves ----
    // quad-reduce row-sum partials (each row's 64 j cols live in one quad)
    #pragma unroll
    for (int mb = 0; mb < 2; mb++)
        #pragma unroll
        for (int rr = 0; rr < 2; rr++) {
            float v = srow[mb][rr];
            v += __shfl_xor_sync(0xffffffffu, v, 1);
            v += __shfl_xor_sync(0xffffffffu, v, 2);
            srow[mb][rr] = v;
        }

    float* Stg = (float*)sm2;                 // [128 threads][68] padded, 34,816 B
    float* Ls  = (float*)(sm2 + 36864);       // [128 rows][2 j-halves]
    if ((lane & 3) == 0) {
        #pragma unroll
        for (int mb = 0; mb < 2; mb++) {
            int row = i0 + mb*16 + (lane>>2);
            Ls[row*2 + jh]     = srow[mb][0];
            Ls[(row+8)*2 + jh] = srow[mb][1];
        }
    }
    if (jh == 1) {
        float* dst = Stg + (rg*32 + lane)*68;
        #pragma unroll
        for (int mb = 0; mb < 2; mb++)
            #pragma unroll
            for (int nb = 0; nb < 8; nb++)
                *(float4*)&dst[(mb*8+nb)*4] = *(float4*)O[mb][nb];
    }
    __syncthreads();

    if (jh == 0) {
        const float g = gamma[0];
        const float* src = Stg + (rg*32 + lane)*68;
        float rs[2][2];
        #pragma unroll
        for (int mb = 0; mb < 2; mb++) {
            int row = i0 + mb*16 + (lane>>2);
            rs[mb][0] = 1.0f / (Ls[row*2]     + Ls[row*2 + 1]);
            rs[mb][1] = 1.0f / (Ls[(row+8)*2] + Ls[(row+8)*2 + 1]);
        }
        #pragma unroll
        for (int mb = 0; mb < 2; mb++) {
            #pragma unroll
            for (int nb = 0; nb < 8; nb++) {
                float4 p = *(const float4*)&src[(mb*8+nb)*4];
                float o0 = O[mb][nb][0] + p.x;
                float o1 = O[mb][nb][1] + p.y;
                float o2 = O[mb][nb][2] + p.z;
                float o3 = O[mb][nb][3] + p.w;
                int irow = ibase + i0 + mb*16 + (lane>>2);
                int c = nb*8 + (lane&3)*2;
                size_t off = (size_t)b*CC*NN + (size_t)c*NN + irow;
                out[off]      = g*(o0*rs[mb][0]) + x[off];
                out[off+NN]   = g*(o1*rs[mb][0]) + x[off+NN];
                out[off+8]    = g*(o2*rs[mb][1]) + x[off+8];
                out[off+NN+8] = g*(o3*rs[mb][1]) + x[off+NN+8];
            }
        }
    }
}

// ---------------------------------------------------------------------------
extern "C" void kernel_launch(void* const* d_in, const int* in_sizes, int n_in,
                              void* d_out, int out_size)
{
    const float* x     = (const float*)d_in[0];
    const float* Wq    = (const float*)d_in[1];
    const float* bq    = (const float*)d_in[2];
    const float* Wk    = (const float*)d_in[3];
    const float* bk    = (const float*)d_in[4];
    const float* Wv    = (const float*)d_in[5];
    const float* bv    = (const float*)d_in[6];
    const float* gamma = (const float*)d_in[7];
    float* out = (float*)d_out;

    const int smem1 = (8192 + 3*64*68) * sizeof(float);  // 84,992 B
    const int smem2 = SMEM2;                             // 143,360 B

    cudaFuncSetAttribute(qkv_kernel,  cudaFuncAttributeMaxDynamicSharedMemorySize, smem1);
    cudaFuncSetAttribute(attn_kernel, cudaFuncAttributeMaxDynamicSharedMemorySize, smem2);

    qkv_kernel<<<dim3(32, 4), 256, smem1>>>(x, Wq, bq, Wk, bk, Wv, bv);
    attn_kernel<<<dim3(32, 4), 256, smem2>>>(x, gamma, out);
}

// round 12
// speedup vs baseline: 1.8354x; 1.2395x over previous
#include <cuda_runtime.h>
#include <cuda_bf16.h>
#include <math.h>

#define BB 4
#define CC 64
#define NN 4096
#define LOG2E 1.4426950408889634f
typedef unsigned int u32;

__device__ __nv_bfloat16 g_QTh[(size_t)BB*NN*CC];
__device__ __nv_bfloat16 g_QTl[(size_t)BB*NN*CC];
__device__ __nv_bfloat16 g_KTh[(size_t)BB*NN*CC];
__device__ __nv_bfloat16 g_KTl[(size_t)BB*NN*CC];
__device__ __nv_bfloat16 g_Vh [(size_t)BB*CC*NN];

__device__ __forceinline__ u32 smem_u32(const void* p){
    u32 a; asm("{ .reg .u64 t; cvta.to.shared.u64 t, %1; cvt.u32.u64 %0, t; }":"=r"(a):"l"(p)); return a;
}
__device__ __forceinline__ u32 pkbf2(float e0, float e1){     // e0 -> low half
    u32 r; asm("cvt.rn.bf16x2.f32 %0, %1, %2;" : "=r"(r) : "f"(e1), "f"(e0)); return r;
}
__device__ __forceinline__ float bfround(float a){
    return __bfloat162float(__float2bfloat16_rn(a));
}
__device__ __forceinline__ float ex2f(float x){
    float r; asm("ex2.approx.f32 %0,%1;" : "=f"(r) : "f"(x)); return r;
}
#define LDSM4(r0,r1,r2,r3,addr) \
    asm volatile("ldmatrix.sync.aligned.m8n8.x4.shared.b16 {%0,%1,%2,%3},[%4];" \
        : "=r"(r0),"=r"(r1),"=r"(r2),"=r"(r3) : "r"(addr))
#define MMA(d,a0,a1,a2,a3,b0,b1) \
    asm volatile("mma.sync.aligned.m16n8k16.row.col.f32.bf16.bf16.f32 " \
        "{%0,%1,%2,%3},{%4,%5,%6,%7},{%8,%9},{%0,%1,%2,%3};" \
        : "+f"((d)[0]),"+f"((d)[1]),"+f"((d)[2]),"+f"((d)[3]) \
        : "r"(a0),"r"(a1),"r"(a2),"r"(a3),"r"(b0),"r"(b1))
#define CPA(dst,src) \
    asm volatile("cp.async.ca.shared.global [%0],[%1],16;"::"r"(dst),"l"(src))
#define CPA_COMMIT() asm volatile("cp.async.commit_group;":::"memory")
#define CPA_WAIT0()  asm volatile("cp.async.wait_group 0;":::"memory")

// per-buffer smem offsets: K rows 144B stride (hi+lo), V rows 272B stride (hi only)
#define SK_H 0
#define SK_L 18432
#define SV_H 36864
#define BUFSZ 54272
#define SMEM2 (2*BUFSZ)   // 108,544 B

// ------------------- Kernel 1: QKV, direct-register bf16 emission -------------------
__global__ void __launch_bounds__(256) qkv_kernel(
    const float* __restrict__ x,
    const float* __restrict__ Wq, const float* __restrict__ bq,
    const float* __restrict__ Wk, const float* __restrict__ bk,
    const float* __restrict__ Wv, const float* __restrict__ bv)
{
    extern __shared__ float sm1[];
    float* xs  = sm1;            // [64][128]
    float* wtq = sm1 + 8192;
    float* wtk = wtq + 64*68;
    float* wtv = wtk + 64*68;
    const int t = threadIdx.x, b = blockIdx.y, nbase = blockIdx.x*128;

    for (int idx = t; idx < 64*64; idx += 256) {
        int o = idx>>6, c = idx&63;
        wtq[c*68+o]=Wq[idx]; wtk[c*68+o]=Wk[idx]; wtv[c*68+o]=Wv[idx];
    }
    const float* xb = x + (size_t)b*CC*NN + nbase;
    for (int i4 = t; i4 < 2048; i4 += 256) {
        int c = i4>>5, n4 = (i4&31)<<2;
        *(float4*)&xs[c*128+n4] = *(const float4*)&xb[(size_t)c*NN+n4];
    }
    __syncthreads();
    const int ty = t>>4, tx = t&15, o0 = ty*4, n0 = tx*8;
    float aq[4][8], ak[4][8], av[4][8];
    #pragma unroll
    for (int r = 0; r < 4; r++) {
        float vq=bq[o0+r], vk=bk[o0+r], vv=bv[o0+r];
        #pragma unroll
        for (int s = 0; s < 8; s++){ aq[r][s]=vq; ak[r][s]=vk; av[r][s]=vv; }
    }
    #pragma unroll 4
    for (int c = 0; c < 64; c++) {
        float wqa[4],wka[4],wva[4],xr[8];
        *(float4*)&wqa[0]=*(float4*)&wtq[c*68+o0];
        *(float4*)&wka[0]=*(float4*)&wtk[c*68+o0];
        *(float4*)&wva[0]=*(float4*)&wtv[c*68+o0];
        *(float4*)&xr[0]=*(float4*)&xs[c*128+n0];
        *(float4*)&xr[4]=*(float4*)&xs[c*128+n0+4];
        #pragma unroll
        for (int r = 0; r < 4; r++)
            #pragma unroll
            for (int s = 0; s < 8; s++){
                aq[r][s]+=wqa[r]*xr[s]; ak[r][s]+=wka[r]*xr[s]; av[r][s]+=wva[r]*xr[s];
            }
    }
    // V (hi only): natural [c][n], coalesced u32 stores
    #pragma unroll
    for (int r = 0; r < 4; r++) {
        size_t off = (size_t)b*CC*NN + (size_t)(o0+r)*NN + nbase + n0;
        #pragma unroll
        for (int m = 0; m < 4; m++)
            *(u32*)(g_Vh+off+2*m) = pkbf2(av[r][2*m], av[r][2*m+1]);
    }
    // Q transposed [n][c], pre-scaled by log2(e); direct 8B packed stores
    #pragma unroll
    for (int s = 0; s < 8; s++) {
        size_t gb = ((size_t)b*NN + nbase + n0 + s)*CC + o0;
        float q0 = aq[0][s]*LOG2E, q1 = aq[1][s]*LOG2E;
        float q2 = aq[2][s]*LOG2E, q3 = aq[3][s]*LOG2E;
        float h0 = bfround(q0), h1 = bfround(q1), h2 = bfround(q2), h3 = bfround(q3);
        uint2 hv; hv.x = pkbf2(h0, h1); hv.y = pkbf2(h2, h3);
        *(uint2*)(g_QTh+gb) = hv;
        uint2 lv; lv.x = pkbf2(q0-h0, q1-h1); lv.y = pkbf2(q2-h2, q3-h3);
        *(uint2*)(g_QTl+gb) = lv;
    }
    // K transposed [n][c]
    #pragma unroll
    for (int s = 0; s < 8; s++) {
        size_t gb = ((size_t)b*NN + nbase + n0 + s)*CC + o0;
        float k0 = ak[0][s], k1 = ak[1][s], k2 = ak[2][s], k3 = ak[3][s];
        float h0 = bfround(k0), h1 = bfround(k1), h2 = bfround(k2), h3 = bfround(k3);
        uint2 hv; hv.x = pkbf2(h0, h1); hv.y = pkbf2(h2, h3);
        *(uint2*)(g_KTh+gb) = hv;
        uint2 lv; lv.x = pkbf2(k0-h0, k1-h1); lv.y = pkbf2(k2-h2, k3-h3);
        *(uint2*)(g_KTl+gb) = lv;
    }
}

// prefetch one K(hi+lo)/V(hi) tile into smem buffer via cp.async
__device__ __forceinline__ void prefetch_tile(
    char* smbuf,
    const __nv_bfloat16* kh, const __nv_bfloat16* kl,
    const __nv_bfloat16* vh, int jt, int t)
{
    const u32 sbuf = smem_u32(smbuf);
    #pragma unroll
    for (int k = 0; k < 4; k++) {
        int idx = t + k*256, row = idx>>3, ch = idx&7;
        CPA(sbuf + SK_H + row*144 + ch*16, (const char*)(kh + (size_t)(jt+row)*CC) + ch*16);
        CPA(sbuf + SK_L + row*144 + ch*16, (const char*)(kl + (size_t)(jt+row)*CC) + ch*16);
    }
    #pragma unroll
    for (int k = 0; k < 4; k++) {
        int idx = t + k*256, row = idx>>4, ch = idx&15;
        CPA(sbuf + SV_H + row*272 + ch*16, (const char*)(vh + (size_t)row*NN + jt) + ch*16);
    }
}

// ------------------- Kernel 2: HMMA flash attention, j-split warps -------------------
// 128 q-rows/CTA, 8 warps: warp = 32 q-rows x 64 j-cols (rg = wid&3, jh = wid>>2).
// GEMM1: 3-product bf16 split. GEMM2: single product (Ph*Vh), errors average out.
__global__ void __launch_bounds__(256) attn_kernel(
    const float* __restrict__ x, const float* __restrict__ gamma,
    float* __restrict__ out)
{
    extern __shared__ __align__(16) char sm2[];
    const int t = threadIdx.x, wid = t>>5, lane = t&31;
    const int rg = wid & 3, jh = wid >> 2;
    const int i0 = rg*32;
    const int jcol0 = jh*64;
    const int b = blockIdx.y, ibase = blockIdx.x*128;

    const __nv_bfloat16* qh = g_QTh + (size_t)b*NN*CC;
    const __nv_bfloat16* ql = g_QTl + (size_t)b*NN*CC;
    const __nv_bfloat16* kh = g_KTh + (size_t)b*NN*CC;
    const __nv_bfloat16* kl = g_KTl + (size_t)b*NN*CC;
    const __nv_bfloat16* vh = g_Vh  + (size_t)b*CC*NN;

    // prefetch tile 0 -> buf0; stage Q -> buf1 K area
    prefetch_tile(sm2, kh, kl, vh, 0, t);
    {
        const u32 sq = smem_u32(sm2 + BUFSZ);
        #pragma unroll
        for (int k = 0; k < 4; k++) {
            int idx = t + k*256, row = idx>>3, ch = idx&7;
            CPA(sq + SK_H + row*144 + ch*16, (const char*)(qh + (size_t)(ibase+row)*CC) + ch*16);
            CPA(sq + SK_L + row*144 + ch*16, (const char*)(ql + (size_t)(ibase+row)*CC) + ch*16);
        }
    }
    CPA_COMMIT();
    CPA_WAIT0();
    __syncthreads();

    // Q A-frags for the warp's two m16 blocks
    u32 qfh[2][4][4], qfl[2][4][4];
    #pragma unroll
    for (int mb = 0; mb < 2; mb++) {
        u32 abase = smem_u32(sm2 + BUFSZ) + (u32)((i0 + mb*16 + (lane&15))*144 + ((lane>>4)*16));
        #pragma unroll
        for (int ks = 0; ks < 4; ks++) {
            LDSM4(qfh[mb][ks][0],qfh[mb][ks][1],qfh[mb][ks][2],qfh[mb][ks][3], abase + ks*32);
            LDSM4(qfl[mb][ks][0],qfl[mb][ks][1],qfl[mb][ks][2],qfl[mb][ks][3], abase + ks*32 + 18432);
        }
    }
    __syncthreads();   // Q staging (buf1) free for tile-1 prefetch

    float O[2][8][4];
    #pragma unroll
    for (int mb = 0; mb < 2; mb++)
        #pragma unroll
        for (int nb = 0; nb < 8; nb++)
            #pragma unroll
            for (int k = 0; k < 4; k++) O[mb][nb][k] = 0.f;
    float srow[2][2] = {{0.f,0.f},{0.f,0.f}};

    for (int tile = 0; tile < 32; tile++) {
        char* cur = sm2 + (tile & 1)*BUFSZ;
        char* nxt = sm2 + ((tile & 1)^1)*BUFSZ;
        if (tile > 0) { CPA_WAIT0(); __syncthreads(); }
        if (tile < 31) { prefetch_tile(nxt, kh, kl, vh, (tile+1)<<7, t); CPA_COMMIT(); }

        const u32 sb = smem_u32(cur);

        // ---- GEMM1: S[32 x 64] = Qh*Kh + Qh*Kl + Ql*Kh ----
        float S[2][8][4];
        #pragma unroll
        for (int nb = 0; nb < 8; nb++) {
            u32 base = sb + SK_H + (u32)(((jcol0 + nb*8 + (lane&7))*144) + ((lane>>3)*16));
            u32 h0,h1,h2,h3,h4,h5,h6,h7, l0,l1,l2,l3,l4,l5,l6,l7;
            LDSM4(h0,h1,h2,h3, base);
            LDSM4(h4,h5,h6,h7, base + 64);
            LDSM4(l0,l1,l2,l3, base + 18432);
            LDSM4(l4,l5,l6,l7, base + 18432 + 64);
            #pragma unroll
            for (int mb = 0; mb < 2; mb++) {
                float* D = S[mb][nb];
                D[0]=D[1]=D[2]=D[3]=0.f;
                MMA(D, qfh[mb][0][0],qfh[mb][0][1],qfh[mb][0][2],qfh[mb][0][3], h0,h1);
                MMA(D, qfh[mb][1][0],qfh[mb][1][1],qfh[mb][1][2],qfh[mb][1][3], h2,h3);
                MMA(D, qfh[mb][2][0],qfh[mb][2][1],qfh[mb][2][2],qfh[mb][2][3], h4,h5);
                MMA(D, qfh[mb][3][0],qfh[mb][3][1],qfh[mb][3][2],qfh[mb][3][3], h6,h7);
                MMA(D, qfh[mb][0][0],qfh[mb][0][1],qfh[mb][0][2],qfh[mb][0][3], l0,l1);
                MMA(D, qfh[mb][1][0],qfh[mb][1][1],qfh[mb][1][2],qfh[mb][1][3], l2,l3);
                MMA(D, qfh[mb][2][0],qfh[mb][2][1],qfh[mb][2][2],qfh[mb][2][3], l4,l5);
                MMA(D, qfh[mb][3][0],qfh[mb][3][1],qfh[mb][3][2],qfh[mb][3][3], l6,l7);
                MMA(D, qfl[mb][0][0],qfl[mb][0][1],qfl[mb][0][2],qfl[mb][0][3], h0,h1);
                MMA(D, qfl[mb][1][0],qfl[mb][1][1],qfl[mb][1][2],qfl[mb][1][3], h2,h3);
                MMA(D, qfl[mb][2][0],qfl[mb][2][1],qfl[mb][2][2],qfl[mb][2][3], h4,h5);
                MMA(D, qfl[mb][3][0],qfl[mb][3][1],qfl[mb][3][2],qfl[mb][3][3], h6,h7);
            }
        }

        // ---- exp2 (Q pre-scaled by log2e), row-sum partials, pack P A-frags ----
        u32 ah[2][4][4];
        #pragma unroll
        for (int mb = 0; mb < 2; mb++) {
            #pragma unroll
            for (int ks = 0; ks < 4; ks++) {
                const float* SA = S[mb][2*ks];
                const float* SB = S[mb][2*ks+1];
                float eA0 = ex2f(SA[0]), eA1 = ex2f(SA[1]);
                float eA2 = ex2f(SA[2]), eA3 = ex2f(SA[3]);
                float eB0 = ex2f(SB[0]), eB1 = ex2f(SB[1]);
                float eB2 = ex2f(SB[2]), eB3 = ex2f(SB[3]);
                srow[mb][0] += (eA0 + eA1) + (eB0 + eB1);
                srow[mb][1] += (eA2 + eA3) + (eB2 + eB3);
                ah[mb][ks][0] = pkbf2(eA0, eA1);
                ah[mb][ks][1] = pkbf2(eA2, eA3);
                ah[mb][ks][2] = pkbf2(eB0, eB1);
                ah[mb][ks][3] = pkbf2(eB2, eB3);
            }
        }

        // ---- GEMM2: O[32 x 64] += Ph*Vh over this warp's j-half ----
        #pragma unroll
        for (int nb = 0; nb < 8; nb++) {
            u32 base = sb + SV_H + (u32)((nb*8 + (lane&7))*272 + jcol0*2 + ((lane>>3)*16));
            u32 v0,v1,v2,v3,v4,v5,v6,v7;
            LDSM4(v0,v1,v2,v3, base);
            LDSM4(v4,v5,v6,v7, base + 64);
            #pragma unroll
            for (int mb = 0; mb < 2; mb++) {
                float* D = O[mb][nb];
                MMA(D, ah[mb][0][0],ah[mb][0][1],ah[mb][0][2],ah[mb][0][3], v0,v1);
                MMA(D, ah[mb][1][0],ah[mb][1][1],ah[mb][1][2],ah[mb][1][3], v2,v3);
                MMA(D, ah[mb][2][0],ah[mb][2][1],ah[mb][2][2],ah[mb][2][3], v4,v5);
                MMA(D, ah[mb][3][0],ah[mb][3][1],ah[mb][3][2],ah[mb][3][3], v6,v7);
            }
        }
    }

    // ---- epilogue: combine j-halves ----
    #pragma unroll
    for (int mb = 0; mb < 2; mb++)
        #pragma unroll
        for (int rr = 0; rr < 2; rr++) {
            float v = srow[mb][rr];
            v += __shfl_xor_sync(0xffffffffu, v, 1);
            v += __shfl_xor_sync(0xffffffffu, v, 2);
            srow[mb][rr] = v;
        }

    float* Stg = (float*)sm2;                 // [128 threads][68] padded
    float* Ls  = (float*)(sm2 + 36864);       // [128 rows][2]
    if ((lane & 3) == 0) {
        #pragma unroll
        for (int mb = 0; mb < 2; mb++) {
            int row = i0 + mb*16 + (lane>>2);
            Ls[row*2 + jh]     = srow[mb][0];
            Ls[(row+8)*2 + jh] = srow[mb][1];
        }
    }
    if (jh == 1) {
        float* dst = Stg + (rg*32 + lane)*68;
        #pragma unroll
        for (int mb = 0; mb < 2; mb++)
            #pragma unroll
            for (int nb = 0; nb < 8; nb++)
                *(float4*)&dst[(mb*8+nb)*4] = *(float4*)O[mb][nb];
    }
    __syncthreads();

    if (jh == 0) {
        const float g = gamma[0];
        const float* src = Stg + (rg*32 + lane)*68;
        float rs[2][2];
        #pragma unroll
        for (int mb = 0; mb < 2; mb++) {
            int row = i0 + mb*16 + (lane>>2);
            rs[mb][0] = 1.0f / (Ls[row*2]     + Ls[row*2 + 1]);
            rs[mb][1] = 1.0f / (Ls[(row+8)*2] + Ls[(row+8)*2 + 1]);
        }
        #pragma unroll
        for (int mb = 0; mb < 2; mb++) {
            #pragma unroll
            for (int nb = 0; nb < 8; nb++) {
                float4 p = *(const float4*)&src[(mb*8+nb)*4];
                float o0 = O[mb][nb][0] + p.x;
                float o1 = O[mb][nb][1] + p.y;
                float o2 = O[mb][nb][2] + p.z;
                float o3 = O[mb][nb][3] + p.w;
                int irow = ibase + i0 + mb*16 + (lane>>2);
                int c = nb*8 + (lane&3)*2;
                size_t off = (size_t)b*CC*NN + (size_t)c*NN + irow;
                out[off]      = g*(o0*rs[mb][0]) + x[off];
                out[off+NN]   = g*(o1*rs[mb][0]) + x[off+NN];
                out[off+8]    = g*(o2*rs[mb][1]) + x[off+8];
                out[off+NN+8] = g*(o3*rs[mb][1]) + x[off+NN+8];
            }
        }
    }
}

// ---------------------------------------------------------------------------
extern "C" void kernel_launch(void* const* d_in, const int* in_sizes, int n_in,
                              void* d_out, int out_size)
{
    const float* x     = (const float*)d_in[0];
    const float* Wq    = (const float*)d_in[1];
    const float* bq    = (const float*)d_in[2];
    const float* Wk    = (const float*)d_in[3];
    const float* bk    = (const float*)d_in[4];
    const float* Wv    = (const float*)d_in[5];
    const float* bv    = (const float*)d_in[6];
    const float* gamma = (const float*)d_in[7];
    float* out = (float*)d_out;

    const int smem1 = (8192 + 3*64*68) * sizeof(float);  // 84,992 B
    const int smem2 = SMEM2;                             // 108,544 B

    cudaFuncSetAttribute(qkv_kernel,  cudaFuncAttributeMaxDynamicSharedMemorySize, smem1);
    cudaFuncSetAttribute(attn_kernel, cudaFuncAttributeMaxDynamicSharedMemorySize, smem2);

    qkv_kernel<<<dim3(32, 4), 256, smem1>>>(x, Wq, bq, Wk, bk, Wv, bv);
    attn_kernel<<<dim3(32, 4), 256, smem2>>>(x, gamma, out);
}

// round 13
// speedup vs baseline: 1.9022x; 1.0364x over previous
#include <cuda_runtime.h>
#include <cuda_bf16.h>
#include <math.h>

#define BB 4
#define CC 64
#define NN 4096
#define LOG2E 1.4426950408889634f
typedef unsigned int u32;

__device__ __nv_bfloat16 g_QTh[(size_t)BB*NN*CC];
__device__ __nv_bfloat16 g_QTl[(size_t)BB*NN*CC];
__device__ __nv_bfloat16 g_KTh[(size_t)BB*NN*CC];
__device__ __nv_bfloat16 g_KTl[(size_t)BB*NN*CC];
__device__ __nv_bfloat16 g_Vh [(size_t)BB*CC*NN];

__device__ __forceinline__ u32 smem_u32(const void* p){
    u32 a; asm("{ .reg .u64 t; cvta.to.shared.u64 t, %1; cvt.u32.u64 %0, t; }":"=r"(a):"l"(p)); return a;
}
__device__ __forceinline__ u32 pkbf2(float e0, float e1){     // e0 -> low half
    u32 r; asm("cvt.rn.bf16x2.f32 %0, %1, %2;" : "=r"(r) : "f"(e1), "f"(e0)); return r;
}
__device__ __forceinline__ float bfround(float a){
    return __bfloat162float(__float2bfloat16_rn(a));
}
__device__ __forceinline__ float ex2f(float x){
    float r; asm("ex2.approx.f32 %0,%1;" : "=f"(r) : "f"(x)); return r;
}
#define LDSM4(r0,r1,r2,r3,addr) \
    asm volatile("ldmatrix.sync.aligned.m8n8.x4.shared.b16 {%0,%1,%2,%3},[%4];" \
        : "=r"(r0),"=r"(r1),"=r"(r2),"=r"(r3) : "r"(addr))
#define MMA(d,a0,a1,a2,a3,b0,b1) \
    asm volatile("mma.sync.aligned.m16n8k16.row.col.f32.bf16.bf16.f32 " \
        "{%0,%1,%2,%3},{%4,%5,%6,%7},{%8,%9},{%0,%1,%2,%3};" \
        : "+f"((d)[0]),"+f"((d)[1]),"+f"((d)[2]),"+f"((d)[3]) \
        : "r"(a0),"r"(a1),"r"(a2),"r"(a3),"r"(b0),"r"(b1))
#define CPA(dst,src) \
    asm volatile("cp.async.ca.shared.global [%0],[%1],16;"::"r"(dst),"l"(src))
#define CPA_COMMIT() asm volatile("cp.async.commit_group;":::"memory")
#define CPA_WAIT0()  asm volatile("cp.async.wait_group 0;":::"memory")

// per-buffer smem offsets: K rows 144B stride (hi+lo), V rows 272B stride (hi only)
#define SK_H 0
#define SK_L 18432
#define SV_H 36864
#define BUFSZ 54272
#define SMEM2 (2*BUFSZ)   // 108,544 B

// ------------------- Kernel 1: QKV, 64-wide n-tiles, 2 CTAs/SM -------------------
__global__ void __launch_bounds__(256) qkv_kernel(
    const float* __restrict__ x,
    const float* __restrict__ Wq, const float* __restrict__ bq,
    const float* __restrict__ Wk, const float* __restrict__ bk,
    const float* __restrict__ Wv, const float* __restrict__ bv)
{
    extern __shared__ float sm1[];
    float* xs  = sm1;            // [64][64]
    float* wtq = sm1 + 4096;     // [64][68]
    float* wtk = wtq + 64*68;
    float* wtv = wtk + 64*68;
    const int t = threadIdx.x, b = blockIdx.y, nbase = blockIdx.x*64;

    for (int idx = t; idx < 64*64; idx += 256) {
        int o = idx>>6, c = idx&63;
        wtq[c*68+o]=Wq[idx]; wtk[c*68+o]=Wk[idx]; wtv[c*68+o]=Wv[idx];
    }
    const float* xb = x + (size_t)b*CC*NN + nbase;
    for (int i4 = t; i4 < 1024; i4 += 256) {
        int c = i4>>4, n4 = (i4&15)<<2;
        *(float4*)&xs[c*64+n4] = *(const float4*)&xb[(size_t)c*NN+n4];
    }
    __syncthreads();
    const int ty = t>>4, tx = t&15, o0 = ty*4, n0 = tx*4;
    float aq[4][4], ak[4][4], av[4][4];
    #pragma unroll
    for (int r = 0; r < 4; r++) {
        float vq=bq[o0+r], vk=bk[o0+r], vv=bv[o0+r];
        #pragma unroll
        for (int s = 0; s < 4; s++){ aq[r][s]=vq; ak[r][s]=vk; av[r][s]=vv; }
    }
    #pragma unroll 4
    for (int c = 0; c < 64; c++) {
        float wqa[4],wka[4],wva[4],xr[4];
        *(float4*)&wqa[0]=*(float4*)&wtq[c*68+o0];
        *(float4*)&wka[0]=*(float4*)&wtk[c*68+o0];
        *(float4*)&wva[0]=*(float4*)&wtv[c*68+o0];
        *(float4*)&xr[0]=*(float4*)&xs[c*64+n0];
        #pragma unroll
        for (int r = 0; r < 4; r++)
            #pragma unroll
            for (int s = 0; s < 4; s++){
                aq[r][s]+=wqa[r]*xr[s]; ak[r][s]+=wka[r]*xr[s]; av[r][s]+=wva[r]*xr[s];
            }
    }
    // V (hi only): natural [c][n]
    #pragma unroll
    for (int r = 0; r < 4; r++) {
        size_t off = (size_t)b*CC*NN + (size_t)(o0+r)*NN + nbase + n0;
        *(u32*)(g_Vh+off)   = pkbf2(av[r][0], av[r][1]);
        *(u32*)(g_Vh+off+2) = pkbf2(av[r][2], av[r][3]);
    }
    // Q transposed [n][c], pre-scaled by log2(e); direct 8B packed stores
    #pragma unroll
    for (int s = 0; s < 4; s++) {
        size_t gb = ((size_t)b*NN + nbase + n0 + s)*CC + o0;
        float q0 = aq[0][s]*LOG2E, q1 = aq[1][s]*LOG2E;
        float q2 = aq[2][s]*LOG2E, q3 = aq[3][s]*LOG2E;
        float h0 = bfround(q0), h1 = bfround(q1), h2 = bfround(q2), h3 = bfround(q3);
        uint2 hv; hv.x = pkbf2(h0, h1); hv.y = pkbf2(h2, h3);
        *(uint2*)(g_QTh+gb) = hv;
        uint2 lv; lv.x = pkbf2(q0-h0, q1-h1); lv.y = pkbf2(q2-h2, q3-h3);
        *(uint2*)(g_QTl+gb) = lv;
    }
    // K transposed [n][c]
    #pragma unroll
    for (int s = 0; s < 4; s++) {
        size_t gb = ((size_t)b*NN + nbase + n0 + s)*CC + o0;
        float k0 = ak[0][s], k1 = ak[1][s], k2 = ak[2][s], k3 = ak[3][s];
        float h0 = bfround(k0), h1 = bfround(k1), h2 = bfround(k2), h3 = bfround(k3);
        uint2 hv; hv.x = pkbf2(h0, h1); hv.y = pkbf2(h2, h3);
        *(uint2*)(g_KTh+gb) = hv;
        uint2 lv; lv.x = pkbf2(k0-h0, k1-h1); lv.y = pkbf2(k2-h2, k3-h3);
        *(uint2*)(g_KTl+gb) = lv;
    }
}

// prefetch one K(hi+lo)/V(hi) tile into smem buffer via cp.async
__device__ __forceinline__ void prefetch_tile(
    char* smbuf,
    const __nv_bfloat16* kh, const __nv_bfloat16* kl,
    const __nv_bfloat16* vh, int jt, int t)
{
    const u32 sbuf = smem_u32(smbuf);
    #pragma unroll
    for (int k = 0; k < 4; k++) {
        int idx = t + k*256, row = idx>>3, ch = idx&7;
        CPA(sbuf + SK_H + row*144 + ch*16, (const char*)(kh + (size_t)(jt+row)*CC) + ch*16);
        CPA(sbuf + SK_L + row*144 + ch*16, (const char*)(kl + (size_t)(jt+row)*CC) + ch*16);
    }
    #pragma unroll
    for (int k = 0; k < 4; k++) {
        int idx = t + k*256, row = idx>>4, ch = idx&15;
        CPA(sbuf + SV_H + row*272 + ch*16, (const char*)(vh + (size_t)row*NN + jt) + ch*16);
    }
}

// ------------------- Kernel 2: HMMA flash attention, half-tile interleave -------------------
// 128 q-rows/CTA, 8 warps: warp = 32 q-rows x 64 j-cols (rg = wid&3, jh = wid>>2).
// Tile body split into two j-halves: GEMM1(4 nb) -> exp2 -> GEMM2(k-steps 2h,2h+1),
// shrinking live registers (S 64->32, ah 32->16) so ptxas can pipeline deeper.
__global__ void __launch_bounds__(256) attn_kernel(
    const float* __restrict__ x, const float* __restrict__ gamma,
    float* __restrict__ out)
{
    extern __shared__ __align__(16) char sm2[];
    const int t = threadIdx.x, wid = t>>5, lane = t&31;
    const int rg = wid & 3, jh = wid >> 2;
    const int i0 = rg*32;
    const int jcol0 = jh*64;
    const int b = blockIdx.y, ibase = blockIdx.x*128;

    const __nv_bfloat16* qh = g_QTh + (size_t)b*NN*CC;
    const __nv_bfloat16* ql = g_QTl + (size_t)b*NN*CC;
    const __nv_bfloat16* kh = g_KTh + (size_t)b*NN*CC;
    const __nv_bfloat16* kl = g_KTl + (size_t)b*NN*CC;
    const __nv_bfloat16* vh = g_Vh  + (size_t)b*CC*NN;

    // prefetch tile 0 -> buf0; stage Q -> buf1 K area
    prefetch_tile(sm2, kh, kl, vh, 0, t);
    {
        const u32 sq = smem_u32(sm2 + BUFSZ);
        #pragma unroll
        for (int k = 0; k < 4; k++) {
            int idx = t + k*256, row = idx>>3, ch = idx&7;
            CPA(sq + SK_H + row*144 + ch*16, (const char*)(qh + (size_t)(ibase+row)*CC) + ch*16);
            CPA(sq + SK_L + row*144 + ch*16, (const char*)(ql + (size_t)(ibase+row)*CC) + ch*16);
        }
    }
    CPA_COMMIT();
    CPA_WAIT0();
    __syncthreads();

    // Q A-frags for the warp's two m16 blocks
    u32 qfh[2][4][4], qfl[2][4][4];
    #pragma unroll
    for (int mb = 0; mb < 2; mb++) {
        u32 abase = smem_u32(sm2 + BUFSZ) + (u32)((i0 + mb*16 + (lane&15))*144 + ((lane>>4)*16));
        #pragma unroll
        for (int ks = 0; ks < 4; ks++) {
            LDSM4(qfh[mb][ks][0],qfh[mb][ks][1],qfh[mb][ks][2],qfh[mb][ks][3], abase + ks*32);
            LDSM4(qfl[mb][ks][0],qfl[mb][ks][1],qfl[mb][ks][2],qfl[mb][ks][3], abase + ks*32 + 18432);
        }
    }
    __syncthreads();   // Q staging (buf1) free for tile-1 prefetch

    float O[2][8][4];
    #pragma unroll
    for (int mb = 0; mb < 2; mb++)
        #pragma unroll
        for (int nb = 0; nb < 8; nb++)
            #pragma unroll
            for (int k = 0; k < 4; k++) O[mb][nb][k] = 0.f;
    float srow[2][2] = {{0.f,0.f},{0.f,0.f}};

    for (int tile = 0; tile < 32; tile++) {
        char* cur = sm2 + (tile & 1)*BUFSZ;
        char* nxt = sm2 + ((tile & 1)^1)*BUFSZ;
        if (tile > 0) { CPA_WAIT0(); __syncthreads(); }
        if (tile < 31) { prefetch_tile(nxt, kh, kl, vh, (tile+1)<<7, t); CPA_COMMIT(); }

        const u32 sb = smem_u32(cur);

        #pragma unroll
        for (int h = 0; h < 2; h++) {
            // ---- GEMM1 half: S[32 x 32] = Qh*Kh + Qh*Kl + Ql*Kh (nb = 4h..4h+3) ----
            float S[2][4][4];
            #pragma unroll
            for (int nbl = 0; nbl < 4; nbl++) {
                int nb = h*4 + nbl;
                u32 base = sb + SK_H + (u32)(((jcol0 + nb*8 + (lane&7))*144) + ((lane>>3)*16));
                u32 h0,h1,h2,h3,h4,h5,h6,h7, l0,l1,l2,l3,l4,l5,l6,l7;
                LDSM4(h0,h1,h2,h3, base);
                LDSM4(h4,h5,h6,h7, base + 64);
                LDSM4(l0,l1,l2,l3, base + 18432);
                LDSM4(l4,l5,l6,l7, base + 18432 + 64);
                #pragma unroll
                for (int mb = 0; mb < 2; mb++) {
                    float* D = S[mb][nbl];
                    D[0]=D[1]=D[2]=D[3]=0.f;
                    MMA(D, qfh[mb][0][0],qfh[mb][0][1],qfh[mb][0][2],qfh[mb][0][3], h0,h1);
                    MMA(D, qfh[mb][1][0],qfh[mb][1][1],qfh[mb][1][2],qfh[mb][1][3], h2,h3);
                    MMA(D, qfh[mb][2][0],qfh[mb][2][1],qfh[mb][2][2],qfh[mb][2][3], h4,h5);
                    MMA(D, qfh[mb][3][0],qfh[mb][3][1],qfh[mb][3][2],qfh[mb][3][3], h6,h7);
                    MMA(D, qfh[mb][0][0],qfh[mb][0][1],qfh[mb][0][2],qfh[mb][0][3], l0,l1);
                    MMA(D, qfh[mb][1][0],qfh[mb][1][1],qfh[mb][1][2],qfh[mb][1][3], l2,l3);
                    MMA(D, qfh[mb][2][0],qfh[mb][2][1],qfh[mb][2][2],qfh[mb][2][3], l4,l5);
                    MMA(D, qfh[mb][3][0],qfh[mb][3][1],qfh[mb][3][2],qfh[mb][3][3], l6,l7);
                    MMA(D, qfl[mb][0][0],qfl[mb][0][1],qfl[mb][0][2],qfl[mb][0][3], h0,h1);
                    MMA(D, qfl[mb][1][0],qfl[mb][1][1],qfl[mb][1][2],qfl[mb][1][3], h2,h3);
                    MMA(D, qfl[mb][2][0],qfl[mb][2][1],qfl[mb][2][2],qfl[mb][2][3], h4,h5);
                    MMA(D, qfl[mb][3][0],qfl[mb][3][1],qfl[mb][3][2],qfl[mb][3][3], h6,h7);
                }
            }

            // ---- exp2 + row-sum partials + pack P A-frags (k-steps 2h, 2h+1) ----
            u32 ahh[2][2][4];
            #pragma unroll
            for (int mb = 0; mb < 2; mb++) {
                #pragma unroll
                for (int ksl = 0; ksl < 2; ksl++) {
                    const float* SA = S[mb][2*ksl];
                    const float* SB = S[mb][2*ksl+1];
                    float eA0 = ex2f(SA[0]), eA1 = ex2f(SA[1]);
                    float eA2 = ex2f(SA[2]), eA3 = ex2f(SA[3]);
                    float eB0 = ex2f(SB[0]), eB1 = ex2f(SB[1]);
                    float eB2 = ex2f(SB[2]), eB3 = ex2f(SB[3]);
                    srow[mb][0] += (eA0 + eA1) + (eB0 + eB1);
                    srow[mb][1] += (eA2 + eA3) + (eB2 + eB3);
                    ahh[mb][ksl][0] = pkbf2(eA0, eA1);
                    ahh[mb][ksl][1] = pkbf2(eA2, eA3);
                    ahh[mb][ksl][2] = pkbf2(eB0, eB1);
                    ahh[mb][ksl][3] = pkbf2(eB2, eB3);
                }
            }

            // ---- GEMM2 half: O += Ph*Vh over k-steps 2h, 2h+1 ----
            #pragma unroll
            for (int nbO = 0; nbO < 8; nbO++) {
                u32 base = sb + SV_H + (u32)((nbO*8 + (lane&7))*272 + jcol0*2 + ((lane>>3)*16)) + h*64;
                u32 v0,v1,v2,v3;
                LDSM4(v0,v1,v2,v3, base);
                #pragma unroll
                for (int mb = 0; mb < 2; mb++) {
                    float* D = O[mb][nbO];
                    MMA(D, ahh[mb][0][0],ahh[mb][0][1],ahh[mb][0][2],ahh[mb][0][3], v0,v1);
                    MMA(D, ahh[mb][1][0],ahh[mb][1][1],ahh[mb][1][2],ahh[mb][1][3], v2,v3);
                }
            }
        }
    }

    // ---- epilogue: combine j-halves ----
    #pragma unroll
    for (int mb = 0; mb < 2; mb++)
        #pragma unroll
        for (int rr = 0; rr < 2; rr++) {
            float v = srow[mb][rr];
            v += __shfl_xor_sync(0xffffffffu, v, 1);
            v += __shfl_xor_sync(0xffffffffu, v, 2);
            srow[mb][rr] = v;
        }

    float* Stg = (float*)sm2;                 // [128 threads][68] padded
    float* Ls  = (float*)(sm2 + 36864);       // [128 rows][2]
    if ((lane & 3) == 0) {
        #pragma unroll
        for (int mb = 0; mb < 2; mb++) {
            int row = i0 + mb*16 + (lane>>2);
            Ls[row*2 + jh]     = srow[mb][0];
            Ls[(row+8)*2 + jh] = srow[mb][1];
        }
    }
    if (jh == 1) {
        float* dst = Stg + (rg*32 + lane)*68;
        #pragma unroll
        for (int mb = 0; mb < 2; mb++)
            #pragma unroll
            for (int nb = 0; nb < 8; nb++)
                *(float4*)&dst[(mb*8+nb)*4] = *(float4*)O[mb][nb];
    }
    __syncthreads();

    if (jh == 0) {
        const float g = gamma[0];
        const float* src = Stg + (rg*32 + lane)*68;
        float rs[2][2];
        #pragma unroll
        for (int mb = 0; mb < 2; mb++) {
            int row = i0 + mb*16 + (lane>>2);
            rs[mb][0] = 1.0f / (Ls[row*2]     + Ls[row*2 + 1]);
            rs[mb][1] = 1.0f / (Ls[(row+8)*2] + Ls[(row+8)*2 + 1]);
        }
        #pragma unroll
        for (int mb = 0; mb < 2; mb++) {
            #pragma unroll
            for (int nb = 0; nb < 8; nb++) {
                float4 p = *(const float4*)&src[(mb*8+nb)*4];
                float o0 = O[mb][nb][0] + p.x;
                float o1 = O[mb][nb][1] + p.y;
                float o2 = O[mb][nb][2] + p.z;
                float o3 = O[mb][nb][3] + p.w;
                int irow = ibase + i0 + mb*16 + (lane>>2);
                int c = nb*8 + (lane&3)*2;
                size_t off = (size_t)b*CC*NN + (size_t)c*NN + irow;
                out[off]      = g*(o0*rs[mb][0]) + x[off];
                out[off+NN]   = g*(o1*rs[mb][0]) + x[off+NN];
                out[off+8]    = g*(o2*rs[mb][1]) + x[off+8];
                out[off+NN+8] = g*(o3*rs[mb][1]) + x[off+NN+8];
            }
        }
    }
}

// ---------------------------------------------------------------------------
extern "C" void kernel_launch(void* const* d_in, const int* in_sizes, int n_in,
                              void* d_out, int out_size)
{
    const float* x     = (const float*)d_in[0];
    const float* Wq    = (const float*)d_in[1];
    const float* bq    = (const float*)d_in[2];
    const float* Wk    = (const float*)d_in[3];
    const float* bk    = (const float*)d_in[4];
    const float* Wv    = (const float*)d_in[5];
    const float* bv    = (const float*)d_in[6];
    const float* gamma = (const float*)d_in[7];
    float* out = (float*)d_out;

    const int smem1 = (4096 + 3*64*68) * sizeof(float);  // 68,608 B -> 2 CTAs/SM
    const int smem2 = SMEM2;                             // 108,544 B

    cudaFuncSetAttribute(qkv_kernel,  cudaFuncAttributeMaxDynamicSharedMemorySize, smem1);
    cudaFuncSetAttribute(attn_kernel, cudaFuncAttributeMaxDynamicSharedMemorySize, smem2);

    qkv_kernel<<<dim3(64, 4), 256, smem1>>>(x, Wq, bq, Wk, bk, Wv, bv);
    attn_kernel<<<dim3(32, 4), 256, smem2>>>(x, gamma, out);
}